// round 1
// baseline (speedup 1.0000x reference)
#include <cuda_runtime.h>
#include <cuda_bf16.h>
#include <math.h>

// Problem constants (fixed by setup_inputs)
#define BATCH 16
#define SEQ   1024
#define CDIM  768
#define HEADS 12
#define HDIM  64
#define QKVC  (3*CDIM)          // 2304
#define MROWS (BATCH*SEQ)       // 16384

// Scratch (allocation-free rule: __device__ globals)
__device__ float g_qkv [(size_t)MROWS * QKVC];   // (B*N, 2304)  q|k|v interleaved per row
__device__ float g_attn[(size_t)MROWS * CDIM];   // (B*N, 768)   attention output

// ---------------------------------------------------------------------------
// SGEMM: C = A(MxK) * B(KxN) + bias,  optional zeta scaling of columns (col%768)
// 128x128 tile, BK=8, 256 threads, 8x8 per thread.
// ---------------------------------------------------------------------------
#define BM 128
#define BN 128
#define BK 8
#define TM 8
#define TN 8

template<bool ZETA>
__device__ __forceinline__ void gemm_core(const float* __restrict__ A,
                                          const float* __restrict__ Bm,
                                          const float* __restrict__ bias,
                                          const float* __restrict__ zeta,
                                          float* __restrict__ C,
                                          int M, int N, int K)
{
    __shared__ float As[BK][BM];
    __shared__ float Bs[BK][BN];

    const int tid = threadIdx.x;
    const int m0 = blockIdx.y * BM;
    const int n0 = blockIdx.x * BN;
    const int tx = tid & 15;
    const int ty = tid >> 4;

    // A tile loader: 128 rows x 8 cols -> one float4 per thread
    const int arow = tid >> 1;
    const int acol = (tid & 1) * 4;
    // B tile loader: 8 rows x 128 cols -> one float4 per thread
    const int brow = tid >> 5;
    const int bcol = (tid & 31) * 4;

    const float* Aptr = A + (size_t)(m0 + arow) * K + acol;
    const float* Bptr = Bm + (size_t)brow * N + n0 + bcol;

    float acc[TM][TN];
    #pragma unroll
    for (int i = 0; i < TM; i++)
        #pragma unroll
        for (int j = 0; j < TN; j++) acc[i][j] = 0.f;

    for (int k0 = 0; k0 < K; k0 += BK) {
        float4 av = *(const float4*)(Aptr + k0);
        float4 bv = *(const float4*)(Bptr + (size_t)k0 * N);
        As[acol + 0][arow] = av.x;
        As[acol + 1][arow] = av.y;
        As[acol + 2][arow] = av.z;
        As[acol + 3][arow] = av.w;
        *(float4*)&Bs[brow][bcol] = bv;
        __syncthreads();

        #pragma unroll
        for (int k = 0; k < BK; k++) {
            float a[TM], b[TN];
            #pragma unroll
            for (int i = 0; i < TM; i++) a[i] = As[k][ty * TM + i];
            #pragma unroll
            for (int j = 0; j < TN; j++) b[j] = Bs[k][tx * TN + j];
            #pragma unroll
            for (int i = 0; i < TM; i++)
                #pragma unroll
                for (int j = 0; j < TN; j++) acc[i][j] += a[i] * b[j];
        }
        __syncthreads();
    }

    // Epilogue: bias (+ zeta) and vectorized store
    #pragma unroll
    for (int i = 0; i < TM; i++) {
        const int row = m0 + ty * TM + i;
        float* Crow = C + (size_t)row * N + n0 + tx * TN;
        float tmp[TN];
        #pragma unroll
        for (int j = 0; j < TN; j++) {
            const int col = n0 + tx * TN + j;
            float v = acc[i][j] + bias[col];
            if (ZETA) v *= zeta[col % CDIM];
            tmp[j] = v;
        }
        *(float4*)(Crow)     = make_float4(tmp[0], tmp[1], tmp[2], tmp[3]);
        *(float4*)(Crow + 4) = make_float4(tmp[4], tmp[5], tmp[6], tmp[7]);
    }
}

__global__ void __launch_bounds__(256)
qkv_gemm_kernel(const float* __restrict__ x, const float* __restrict__ W,
                const float* __restrict__ bias, const float* __restrict__ zeta)
{
    gemm_core<true>(x, W, bias, zeta, g_qkv, MROWS, QKVC, CDIM);
}

__global__ void __launch_bounds__(256)
proj_gemm_kernel(const float* __restrict__ W, const float* __restrict__ bias,
                 float* __restrict__ out)
{
    gemm_core<false>(g_attn, W, bias, nullptr, out, MROWS, CDIM, CDIM);
}

// ---------------------------------------------------------------------------
// Flash attention, fp32. One thread = one query row. Block = 128 rows of one
// (b,h). K/V streamed through smem in 64-key tiles. Online softmax with
// deferred rescale (rescale only on new max: ~ln(N) events per row).
// ---------------------------------------------------------------------------
#define KT 64          // keys per tile
#define VPAD 68        // padded row stride (floats) to spread smem banks

__global__ void __launch_bounds__(128)
attn_kernel(const unsigned char* __restrict__ mask)
{
    __shared__ float Ks[KT][VPAD];
    __shared__ float Vs[KT][VPAD];

    const int qt  = blockIdx.x;   // 0..7
    const int h   = blockIdx.y;   // 0..11
    const int b   = blockIdx.z;   // 0..15
    const int row = qt * 128 + threadIdx.x;

    const float* qptr  = g_qkv + (size_t)(b * SEQ + row) * QKVC + h * HDIM;           // q
    const float* kbase = g_qkv + (size_t)(b * SEQ) * QKVC + CDIM     + h * HDIM;      // k
    const float* vbase = g_qkv + (size_t)(b * SEQ) * QKVC + 2 * CDIM + h * HDIM;      // v
    const unsigned char* mrow = mask + b * SEQ;

    const float scale = 0.125f;   // d^-0.5, d=64

    float q[HDIM];
    #pragma unroll
    for (int i = 0; i < 16; i++) {
        float4 t = *(const float4*)(qptr + i * 4);
        q[4*i+0] = t.x * scale; q[4*i+1] = t.y * scale;
        q[4*i+2] = t.z * scale; q[4*i+3] = t.w * scale;
    }

    float o[HDIM];
    #pragma unroll
    for (int i = 0; i < HDIM; i++) o[i] = 0.f;
    float m = -1e30f;
    float l = 0.f;

    for (int kt = 0; kt < SEQ / KT; kt++) {
        __syncthreads();
        // Cooperative load of K/V tiles (64 rows x 16 float4 each)
        for (int i = threadIdx.x; i < KT * 16; i += 128) {
            const int r  = i >> 4;
            const int c4 = (i & 15) * 4;
            const size_t goff = (size_t)(kt * KT + r) * QKVC + c4;
            *(float4*)&Ks[r][c4] = *(const float4*)(kbase + goff);
            *(float4*)&Vs[r][c4] = *(const float4*)(vbase + goff);
        }
        __syncthreads();

        #pragma unroll 1
        for (int key = 0; key < KT; key++) {
            const float* kr = &Ks[key][0];
            float s0 = 0.f, s1 = 0.f, s2 = 0.f, s3 = 0.f;
            #pragma unroll
            for (int i4 = 0; i4 < 16; i4++) {
                float4 kv = *(const float4*)(kr + i4 * 4);
                s0 += q[4*i4+0] * kv.x;
                s1 += q[4*i4+1] * kv.y;
                s2 += q[4*i4+2] * kv.z;
                s3 += q[4*i4+3] * kv.w;
            }
            float s = (s0 + s1) + (s2 + s3);
            if (mrow[kt * KT + key]) s = -3e30f;   // masked key: below m init, exp -> 0

            if (s > m) {           // rare after warmup: amortized O(log N) per row
                const float corr = __expf(m - s);
                l *= corr;
                #pragma unroll
                for (int i = 0; i < HDIM; i++) o[i] *= corr;
                m = s;
            }
            const float p = __expf(s - m);
            l += p;
            const float* vr = &Vs[key][0];
            #pragma unroll
            for (int i4 = 0; i4 < 16; i4++) {
                float4 vv = *(const float4*)(vr + i4 * 4);
                o[4*i4+0] += p * vv.x;
                o[4*i4+1] += p * vv.y;
                o[4*i4+2] += p * vv.z;
                o[4*i4+3] += p * vv.w;
            }
        }
    }

    const float inv = 1.f / l;
    float* optr = g_attn + (size_t)(b * SEQ + row) * CDIM + h * HDIM;
    #pragma unroll
    for (int i4 = 0; i4 < 16; i4++) {
        float4 vv = make_float4(o[4*i4+0] * inv, o[4*i4+1] * inv,
                                o[4*i4+2] * inv, o[4*i4+3] * inv);
        *(float4*)(optr + i4 * 4) = vv;
    }
}

// ---------------------------------------------------------------------------
// Launch
// ---------------------------------------------------------------------------
extern "C" void kernel_launch(void* const* d_in, const int* in_sizes, int n_in,
                              void* d_out, int out_size)
{
    (void)in_sizes; (void)n_in; (void)out_size;
    const float* x      = (const float*)d_in[0];
    const float* W_qkv  = (const float*)d_in[1];
    const float* b_qkv  = (const float*)d_in[2];
    const float* zeta   = (const float*)d_in[3];
    const float* W_proj = (const float*)d_in[4];
    const float* b_proj = (const float*)d_in[5];
    const unsigned char* mask = (const unsigned char*)d_in[6];
    float* out = (float*)d_out;

    dim3 g1(QKVC / BN, MROWS / BM);      // 18 x 128
    qkv_gemm_kernel<<<g1, 256>>>(x, W_qkv, b_qkv, zeta);

    dim3 ga(SEQ / 128, HEADS, BATCH);    // 8 x 12 x 16
    attn_kernel<<<ga, 128>>>(mask);

    dim3 g2(CDIM / BN, MROWS / BM);      // 6 x 128
    proj_gemm_kernel<<<g2, 256>>>(W_proj, b_proj, out);
}

// round 3
// speedup vs baseline: 1.1715x; 1.1715x over previous
#include <cuda_runtime.h>
#include <cuda_bf16.h>
#include <math.h>
#include <stdint.h>

// Problem constants
#define BATCH 16
#define SEQ   1024
#define CDIM  768
#define HEADS 12
#define HDIM  64
#define QKVC  2304
#define MROWS 16384

// ---------------------------------------------------------------------------
// Scratch (__device__ globals; allocation-free rule)
// ---------------------------------------------------------------------------
__device__ __align__(128) __nv_bfloat16 g_xh [(size_t)MROWS * CDIM];
__device__ __align__(128) __nv_bfloat16 g_xl [(size_t)MROWS * CDIM];
__device__ __align__(128) __nv_bfloat16 g_wqh[(size_t)QKVC  * CDIM];   // W_qkv^T [n][k]
__device__ __align__(128) __nv_bfloat16 g_wql[(size_t)QKVC  * CDIM];
__device__ __align__(128) __nv_bfloat16 g_wph[(size_t)CDIM  * CDIM];   // W_proj^T [n][k]
__device__ __align__(128) __nv_bfloat16 g_wpl[(size_t)CDIM  * CDIM];
__device__ __align__(128) float         g_qkv[(size_t)MROWS * QKVC];   // fp32 gated qkv
__device__ __align__(128) __nv_bfloat16 g_ah [(size_t)MROWS * CDIM];   // attn out hi
__device__ __align__(128) __nv_bfloat16 g_al [(size_t)MROWS * CDIM];   // attn out lo

// ---------------------------------------------------------------------------
// PTX helpers (baseline compute_103 features only: cp.async, ldmatrix, mma.sync)
// ---------------------------------------------------------------------------
__device__ __forceinline__ uint32_t smem_u32(const void* p) {
    uint32_t a;
    asm("{ .reg .u64 t; cvta.to.shared.u64 t, %1; cvt.u32.u64 %0, t; }" : "=r"(a) : "l"(p));
    return a;
}
#define CP_ASYNC16(dst, src) \
    asm volatile("cp.async.cg.shared.global [%0], [%1], 16;" :: "r"(dst), "l"(src))
#define CP_COMMIT() asm volatile("cp.async.commit_group;" ::: "memory")
#define CP_WAIT(n)  asm volatile("cp.async.wait_group %0;" :: "n"(n) : "memory")

#define LDSM_X4(r0, r1, r2, r3, addr) \
    asm volatile("ldmatrix.sync.aligned.m8n8.x4.shared.b16 {%0,%1,%2,%3}, [%4];" \
        : "=r"(r0), "=r"(r1), "=r"(r2), "=r"(r3) : "r"(addr))

#define MMA_BF16(d, a, b0r, b1r) \
    asm volatile("mma.sync.aligned.m16n8k16.row.col.f32.bf16.bf16.f32 " \
        "{%0,%1,%2,%3},{%4,%5,%6,%7},{%8,%9},{%0,%1,%2,%3};" \
        : "+f"((d)[0]), "+f"((d)[1]), "+f"((d)[2]), "+f"((d)[3]) \
        : "r"((a)[0]), "r"((a)[1]), "r"((a)[2]), "r"((a)[3]), "r"(b0r), "r"(b1r))

// ---------------------------------------------------------------------------
// Conversion kernels
// ---------------------------------------------------------------------------
__global__ void split_x_kernel(const float* __restrict__ x)
{
    int i = blockIdx.x * blockDim.x + threadIdx.x;   // float4 index
    if (i >= MROWS * CDIM / 4) return;
    float4 v = ((const float4*)x)[i];
    float f[4] = {v.x, v.y, v.z, v.w};
    __nv_bfloat16 h[4], l[4];
    #pragma unroll
    for (int j = 0; j < 4; j++) {
        h[j] = __float2bfloat16(f[j]);
        l[j] = __float2bfloat16(f[j] - __bfloat162float(h[j]));
    }
    ((uint2*)g_xh)[i] = *(uint2*)h;
    ((uint2*)g_xl)[i] = *(uint2*)l;
}

// W (768 x Nd fp32, row-major) -> W^T hi/lo (Nd x 768 bf16), tiled+coalesced
template<bool QKV>
__global__ void wtrans_kernel(const float* __restrict__ W)
{
    __shared__ float tile[32][33];
    const int Nd = QKV ? QKVC : CDIM;
    __nv_bfloat16* oh = QKV ? g_wqh : g_wph;
    __nv_bfloat16* ol = QKV ? g_wql : g_wpl;
    const int n0 = blockIdx.x * 32;
    const int k0 = blockIdx.y * 32;
    const int tx = threadIdx.x, ty = threadIdx.y;   // (32, 8)

    #pragma unroll
    for (int j = 0; j < 4; j++)
        tile[ty + j * 8][tx] = W[(size_t)(k0 + ty + j * 8) * Nd + n0 + tx];
    __syncthreads();
    #pragma unroll
    for (int j = 0; j < 4; j++) {
        const int n = n0 + ty + j * 8;
        const int k = k0 + tx;
        float v = tile[tx][ty + j * 8];
        __nv_bfloat16 h = __float2bfloat16(v);
        oh[(size_t)n * CDIM + k] = h;
        ol[(size_t)n * CDIM + k] = __float2bfloat16(v - __bfloat162float(h));
    }
}

// ---------------------------------------------------------------------------
// HMMA split-bf16 GEMM: C(M x N) = A(M x 768) * B^T(N x 768) + bias [*zeta]
// CTA tile 128x128, BK=64, double-buffered cp.async, 8 warps (2m x 4n),
// warp tile 64x32, mma.sync m16n8k16, 3-product bf16 emulation.
// ---------------------------------------------------------------------------
#define TILE_B   16384            // one 128x64 bf16 tile (SW128-xor swizzled)
#define STAGE_B  (4 * TILE_B)     // Ah | Al | Bh | Bl
#define GEMM_SMEM (2 * STAGE_B)   // 131072

template<bool QKV>
__global__ void __launch_bounds__(256, 1)
gemm_hmma_kernel(const float* __restrict__ bias,
                 const float* __restrict__ zeta,
                 float* __restrict__ Cout)
{
    const int N = QKV ? QKVC : CDIM;
    const __nv_bfloat16* Ah = QKV ? g_xh  : g_ah;
    const __nv_bfloat16* Al = QKV ? g_xl  : g_al;
    const __nv_bfloat16* Bh = QKV ? g_wqh : g_wph;
    const __nv_bfloat16* Bl = QKV ? g_wql : g_wpl;
    float* C = QKV ? g_qkv : Cout;

    extern __shared__ char smem[];
    const uint32_t sb = smem_u32(smem);
    const int tid  = threadIdx.x;
    const int lane = tid & 31;
    const int wid  = tid >> 5;
    const int wm   = (wid >> 2) * 64;    // 0 / 64
    const int wn   = (wid & 3) * 32;     // 0 / 32 / 64 / 96
    const int m0   = blockIdx.y * 128;
    const int n0   = blockIdx.x * 128;

    const __nv_bfloat16* gsrc[4] = {
        Ah + (size_t)m0 * CDIM, Al + (size_t)m0 * CDIM,
        Bh + (size_t)n0 * CDIM, Bl + (size_t)n0 * CDIM };

    float acc[4][4][4];
    #pragma unroll
    for (int a = 0; a < 4; a++)
        #pragma unroll
        for (int b = 0; b < 4; b++)
            #pragma unroll
            for (int c = 0; c < 4; c++) acc[a][b][c] = 0.f;

    auto load_stage = [&](int chunk, int stage) {
        const int k0 = chunk * 64;
        #pragma unroll
        for (int t = 0; t < 4; t++) {
            const __nv_bfloat16* g = gsrc[t];
            const uint32_t sbase = sb + stage * STAGE_B + t * TILE_B;
            #pragma unroll
            for (int j = 0; j < 4; j++) {
                const int i = tid + j * 256;        // 0..1023
                const int r = i >> 3;               // row 0..127
                const int c = i & 7;                // 16B col 0..7
                const uint32_t soff = sbase + r * 128 + ((c ^ (r & 7)) << 4);
                CP_ASYNC16(soff, g + (size_t)r * CDIM + k0 + c * 8);
            }
        }
        CP_COMMIT();
    };

    load_stage(0, 0);

    #pragma unroll 1
    for (int ch = 0; ch < CDIM / 64; ch++) {
        if (ch + 1 < CDIM / 64) { load_stage(ch + 1, (ch + 1) & 1); CP_WAIT(1); }
        else                    { CP_WAIT(0); }
        __syncthreads();

        const uint32_t st = sb + (ch & 1) * STAGE_B;
        #pragma unroll
        for (int kb = 0; kb < 4; kb++) {
            uint32_t ah[4][4], al[4][4];
            #pragma unroll
            for (int mt = 0; mt < 4; mt++) {
                const int row = wm + mt * 16 + (lane & 15);
                const int col = kb * 2 + (lane >> 4);
                const uint32_t off = row * 128 + ((col ^ (row & 7)) << 4);
                LDSM_X4(ah[mt][0], ah[mt][1], ah[mt][2], ah[mt][3], st + 0 * TILE_B + off);
                LDSM_X4(al[mt][0], al[mt][1], al[mt][2], al[mt][3], st + 1 * TILE_B + off);
            }
            uint32_t bh[2][4], bl[2][4];
            #pragma unroll
            for (int nt = 0; nt < 2; nt++) {
                const int row = wn + nt * 16 + (lane & 15);
                const int col = kb * 2 + (lane >> 4);
                const uint32_t off = row * 128 + ((col ^ (row & 7)) << 4);
                LDSM_X4(bh[nt][0], bh[nt][1], bh[nt][2], bh[nt][3], st + 2 * TILE_B + off);
                LDSM_X4(bl[nt][0], bl[nt][1], bl[nt][2], bl[nt][3], st + 3 * TILE_B + off);
            }
            #pragma unroll
            for (int mt = 0; mt < 4; mt++) {
                #pragma unroll
                for (int n8 = 0; n8 < 4; n8++) {
                    const int t2 = n8 >> 1, s2 = n8 & 1;
                    MMA_BF16(acc[mt][n8], ah[mt], bh[t2][s2], bh[t2][s2 + 2]);
                    MMA_BF16(acc[mt][n8], ah[mt], bl[t2][s2], bl[t2][s2 + 2]);
                    MMA_BF16(acc[mt][n8], al[mt], bh[t2][s2], bh[t2][s2 + 2]);
                }
            }
        }
        __syncthreads();
    }

    // Epilogue: bias (+zeta for QKV), float2 stores
    const int quad = lane >> 2;          // 0..7
    const int tq   = (lane & 3) * 2;
    #pragma unroll
    for (int mt = 0; mt < 4; mt++) {
        #pragma unroll
        for (int n8 = 0; n8 < 4; n8++) {
            const int col = n0 + wn + n8 * 8 + tq;
            float b0 = bias[col], b1 = bias[col + 1];
            float z0 = 1.f, z1 = 1.f;
            if (QKV) { z0 = zeta[col % CDIM]; z1 = zeta[(col + 1) % CDIM]; }
            const int row = m0 + wm + mt * 16 + quad;
            float2 v0 = { (acc[mt][n8][0] + b0) * z0, (acc[mt][n8][1] + b1) * z1 };
            float2 v1 = { (acc[mt][n8][2] + b0) * z0, (acc[mt][n8][3] + b1) * z1 };
            *(float2*)(C + (size_t)row * N + col)       = v0;
            *(float2*)(C + (size_t)(row + 8) * N + col) = v1;
        }
    }
}

// ---------------------------------------------------------------------------
// Flash attention, fp32 SIMT (unchanged). Epilogue emits bf16 hi/lo for proj.
// ---------------------------------------------------------------------------
#define KT 64
#define VPAD 68

__global__ void __launch_bounds__(128)
attn_kernel(const unsigned char* __restrict__ mask)
{
    __shared__ float Ks[KT][VPAD];
    __shared__ float Vs[KT][VPAD];

    const int qt  = blockIdx.x;
    const int h   = blockIdx.y;
    const int b   = blockIdx.z;
    const int row = qt * 128 + threadIdx.x;

    const float* qptr  = g_qkv + (size_t)(b * SEQ + row) * QKVC + h * HDIM;
    const float* kbase = g_qkv + (size_t)(b * SEQ) * QKVC + CDIM     + h * HDIM;
    const float* vbase = g_qkv + (size_t)(b * SEQ) * QKVC + 2 * CDIM + h * HDIM;
    const unsigned char* mrow = mask + b * SEQ;

    const float scale = 0.125f;

    float q[HDIM];
    #pragma unroll
    for (int i = 0; i < 16; i++) {
        float4 t = *(const float4*)(qptr + i * 4);
        q[4*i+0] = t.x * scale; q[4*i+1] = t.y * scale;
        q[4*i+2] = t.z * scale; q[4*i+3] = t.w * scale;
    }

    float o[HDIM];
    #pragma unroll
    for (int i = 0; i < HDIM; i++) o[i] = 0.f;
    float m = -1e30f;
    float l = 0.f;

    for (int kt = 0; kt < SEQ / KT; kt++) {
        __syncthreads();
        for (int i = threadIdx.x; i < KT * 16; i += 128) {
            const int r  = i >> 4;
            const int c4 = (i & 15) * 4;
            const size_t goff = (size_t)(kt * KT + r) * QKVC + c4;
            *(float4*)&Ks[r][c4] = *(const float4*)(kbase + goff);
            *(float4*)&Vs[r][c4] = *(const float4*)(vbase + goff);
        }
        __syncthreads();

        #pragma unroll 1
        for (int key = 0; key < KT; key++) {
            const float* kr = &Ks[key][0];
            float s0 = 0.f, s1 = 0.f, s2 = 0.f, s3 = 0.f;
            #pragma unroll
            for (int i4 = 0; i4 < 16; i4++) {
                float4 kv = *(const float4*)(kr + i4 * 4);
                s0 += q[4*i4+0] * kv.x;
                s1 += q[4*i4+1] * kv.y;
                s2 += q[4*i4+2] * kv.z;
                s3 += q[4*i4+3] * kv.w;
            }
            float s = (s0 + s1) + (s2 + s3);
            if (mrow[kt * KT + key]) s = -3e30f;

            if (s > m) {
                const float corr = __expf(m - s);
                l *= corr;
                #pragma unroll
                for (int i = 0; i < HDIM; i++) o[i] *= corr;
                m = s;
            }
            const float p = __expf(s - m);
            l += p;
            const float* vr = &Vs[key][0];
            #pragma unroll
            for (int i4 = 0; i4 < 16; i4++) {
                float4 vv = *(const float4*)(vr + i4 * 4);
                o[4*i4+0] += p * vv.x;
                o[4*i4+1] += p * vv.y;
                o[4*i4+2] += p * vv.z;
                o[4*i4+3] += p * vv.w;
            }
        }
    }

    const float inv = 1.f / l;
    const size_t obase = (size_t)(b * SEQ + row) * CDIM + h * HDIM;
    #pragma unroll
    for (int i2 = 0; i2 < 32; i2++) {
        float v0 = o[2*i2+0] * inv;
        float v1 = o[2*i2+1] * inv;
        __nv_bfloat16 h0 = __float2bfloat16(v0);
        __nv_bfloat16 h1 = __float2bfloat16(v1);
        __nv_bfloat162 hi; hi.x = h0; hi.y = h1;
        __nv_bfloat162 lo;
        lo.x = __float2bfloat16(v0 - __bfloat162float(h0));
        lo.y = __float2bfloat16(v1 - __bfloat162float(h1));
        *(__nv_bfloat162*)(g_ah + obase + 2*i2) = hi;
        *(__nv_bfloat162*)(g_al + obase + 2*i2) = lo;
    }
}

// ---------------------------------------------------------------------------
// Launch
// ---------------------------------------------------------------------------
extern "C" void kernel_launch(void* const* d_in, const int* in_sizes, int n_in,
                              void* d_out, int out_size)
{
    (void)in_sizes; (void)n_in; (void)out_size;
    const float* x      = (const float*)d_in[0];
    const float* W_qkv  = (const float*)d_in[1];
    const float* b_qkv  = (const float*)d_in[2];
    const float* zeta   = (const float*)d_in[3];
    const float* W_proj = (const float*)d_in[4];
    const float* b_proj = (const float*)d_in[5];
    const unsigned char* mask = (const unsigned char*)d_in[6];
    float* out = (float*)d_out;

    cudaFuncSetAttribute(gemm_hmma_kernel<true>,
                         cudaFuncAttributeMaxDynamicSharedMemorySize, GEMM_SMEM);
    cudaFuncSetAttribute(gemm_hmma_kernel<false>,
                         cudaFuncAttributeMaxDynamicSharedMemorySize, GEMM_SMEM);

    // 1) conversions
    split_x_kernel<<<(MROWS * CDIM / 4 + 255) / 256, 256>>>(x);
    {
        dim3 b(32, 8);
        wtrans_kernel<true ><<<dim3(QKVC / 32, CDIM / 32), b>>>(W_qkv);
        wtrans_kernel<false><<<dim3(CDIM / 32, CDIM / 32), b>>>(W_proj);
    }
    // 2) QKV GEMM (HMMA) with bias+zeta epilogue -> g_qkv fp32
    gemm_hmma_kernel<true><<<dim3(QKVC / 128, MROWS / 128), 256, GEMM_SMEM>>>(b_qkv, zeta, nullptr);
    // 3) attention (fp32 SIMT), emits bf16 hi/lo
    {
        dim3 ga(SEQ / 128, HEADS, BATCH);
        attn_kernel<<<ga, 128>>>(mask);
    }
    // 4) projection GEMM (HMMA) -> out
    gemm_hmma_kernel<false><<<dim3(CDIM / 128, MROWS / 128), 256, GEMM_SMEM>>>(b_proj, nullptr, out);
}

// round 4
// speedup vs baseline: 2.9987x; 2.5597x over previous
#include <cuda_runtime.h>
#include <cuda_bf16.h>
#include <math.h>
#include <stdint.h>

// Problem constants
#define BATCH 16
#define SEQ   1024
#define CDIM  768
#define HEADS 12
#define HDIM  64
#define QKVC  2304
#define MROWS 16384

// ---------------------------------------------------------------------------
// Scratch (__device__ globals; allocation-free rule)
// ---------------------------------------------------------------------------
#define HELEMS ((size_t)BATCH * HEADS * SEQ * HDIM)   // 12.6M per tensor
__device__ __align__(128) __nv_bfloat16 g_xh [(size_t)MROWS * CDIM];
__device__ __align__(128) __nv_bfloat16 g_xl [(size_t)MROWS * CDIM];
__device__ __align__(128) __nv_bfloat16 g_wqh[(size_t)QKVC  * CDIM];   // W_qkv^T [n][k]
__device__ __align__(128) __nv_bfloat16 g_wql[(size_t)QKVC  * CDIM];
__device__ __align__(128) __nv_bfloat16 g_wph[(size_t)CDIM  * CDIM];   // W_proj^T [n][k]
__device__ __align__(128) __nv_bfloat16 g_wpl[(size_t)CDIM  * CDIM];
__device__ __align__(128) __nv_bfloat16 g_qh[HELEMS], g_ql[HELEMS];    // (b,h,n,d) q*0.125
__device__ __align__(128) __nv_bfloat16 g_kh[HELEMS], g_kl[HELEMS];
__device__ __align__(128) __nv_bfloat16 g_vh[HELEMS], g_vl[HELEMS];
__device__ __align__(128) __nv_bfloat16 g_ah [(size_t)MROWS * CDIM];   // attn out hi
__device__ __align__(128) __nv_bfloat16 g_al [(size_t)MROWS * CDIM];   // attn out lo

// ---------------------------------------------------------------------------
// PTX helpers (baseline compute_103 features only)
// ---------------------------------------------------------------------------
__device__ __forceinline__ uint32_t smem_u32(const void* p) {
    uint32_t a;
    asm("{ .reg .u64 t; cvta.to.shared.u64 t, %1; cvt.u32.u64 %0, t; }" : "=r"(a) : "l"(p));
    return a;
}
#define CP_ASYNC16(dst, src) \
    asm volatile("cp.async.cg.shared.global [%0], [%1], 16;" :: "r"(dst), "l"(src))
#define CP_COMMIT() asm volatile("cp.async.commit_group;" ::: "memory")
#define CP_WAIT(n)  asm volatile("cp.async.wait_group %0;" :: "n"(n) : "memory")

#define LDSM_X4(r0, r1, r2, r3, addr) \
    asm volatile("ldmatrix.sync.aligned.m8n8.x4.shared.b16 {%0,%1,%2,%3}, [%4];" \
        : "=r"(r0), "=r"(r1), "=r"(r2), "=r"(r3) : "r"(addr))
#define LDSM_X4_T(r0, r1, r2, r3, addr) \
    asm volatile("ldmatrix.sync.aligned.m8n8.x4.trans.shared.b16 {%0,%1,%2,%3}, [%4];" \
        : "=r"(r0), "=r"(r1), "=r"(r2), "=r"(r3) : "r"(addr))

#define MMA_BF16(d, a, b0r, b1r) \
    asm volatile("mma.sync.aligned.m16n8k16.row.col.f32.bf16.bf16.f32 " \
        "{%0,%1,%2,%3},{%4,%5,%6,%7},{%8,%9},{%0,%1,%2,%3};" \
        : "+f"((d)[0]), "+f"((d)[1]), "+f"((d)[2]), "+f"((d)[3]) \
        : "r"((a)[0]), "r"((a)[1]), "r"((a)[2]), "r"((a)[3]), "r"(b0r), "r"(b1r))

// split two floats into packed bf16 hi / lo pairs
__device__ __forceinline__ void split2(float a, float b, uint32_t& hi, uint32_t& lo) {
    __nv_bfloat16 ah = __float2bfloat16(a), bh = __float2bfloat16(b);
    __nv_bfloat162 h2; h2.x = ah; h2.y = bh;
    __nv_bfloat162 l2;
    l2.x = __float2bfloat16(a - __bfloat162float(ah));
    l2.y = __float2bfloat16(b - __bfloat162float(bh));
    hi = *(uint32_t*)&h2; lo = *(uint32_t*)&l2;
}

// ---------------------------------------------------------------------------
// Conversion kernels
// ---------------------------------------------------------------------------
__global__ void split_x_kernel(const float* __restrict__ x)
{
    int i = blockIdx.x * blockDim.x + threadIdx.x;
    if (i >= MROWS * CDIM / 4) return;
    float4 v = ((const float4*)x)[i];
    float f[4] = {v.x, v.y, v.z, v.w};
    __nv_bfloat16 h[4], l[4];
    #pragma unroll
    for (int j = 0; j < 4; j++) {
        h[j] = __float2bfloat16(f[j]);
        l[j] = __float2bfloat16(f[j] - __bfloat162float(h[j]));
    }
    ((uint2*)g_xh)[i] = *(uint2*)h;
    ((uint2*)g_xl)[i] = *(uint2*)l;
}

template<bool QKV>
__global__ void wtrans_kernel(const float* __restrict__ W)
{
    __shared__ float tile[32][33];
    const int Nd = QKV ? QKVC : CDIM;
    __nv_bfloat16* oh = QKV ? g_wqh : g_wph;
    __nv_bfloat16* ol = QKV ? g_wql : g_wpl;
    const int n0 = blockIdx.x * 32;
    const int k0 = blockIdx.y * 32;
    const int tx = threadIdx.x, ty = threadIdx.y;

    #pragma unroll
    for (int j = 0; j < 4; j++)
        tile[ty + j * 8][tx] = W[(size_t)(k0 + ty + j * 8) * Nd + n0 + tx];
    __syncthreads();
    #pragma unroll
    for (int j = 0; j < 4; j++) {
        const int n = n0 + ty + j * 8;
        const int k = k0 + tx;
        float v = tile[tx][ty + j * 8];
        __nv_bfloat16 h = __float2bfloat16(v);
        oh[(size_t)n * CDIM + k] = h;
        ol[(size_t)n * CDIM + k] = __float2bfloat16(v - __bfloat162float(h));
    }
}

// ---------------------------------------------------------------------------
// HMMA split-bf16 GEMM (128x128 tile, BK=64, cp.async double buffer)
// QKV=true : C scattered to per-head q/k/v hi/lo arrays (q scaled 0.125)
// QKV=false: C = attn_out @ Wp + bias -> Cout fp32
// ---------------------------------------------------------------------------
#define TILE_B   16384
#define STAGE_B  (4 * TILE_B)
#define GEMM_SMEM (2 * STAGE_B)

template<bool QKV>
__global__ void __launch_bounds__(256, 1)
gemm_hmma_kernel(const float* __restrict__ bias,
                 const float* __restrict__ zeta,
                 float* __restrict__ Cout)
{
    const int N = QKV ? QKVC : CDIM;
    const __nv_bfloat16* Ah = QKV ? g_xh  : g_ah;
    const __nv_bfloat16* Al = QKV ? g_xl  : g_al;
    const __nv_bfloat16* Bh = QKV ? g_wqh : g_wph;
    const __nv_bfloat16* Bl = QKV ? g_wql : g_wpl;

    extern __shared__ char smem[];
    const uint32_t sb = smem_u32(smem);
    const int tid  = threadIdx.x;
    const int lane = tid & 31;
    const int wid  = tid >> 5;
    const int wm   = (wid >> 2) * 64;
    const int wn   = (wid & 3) * 32;
    const int m0   = blockIdx.y * 128;
    const int n0   = blockIdx.x * 128;

    const __nv_bfloat16* gsrc[4] = {
        Ah + (size_t)m0 * CDIM, Al + (size_t)m0 * CDIM,
        Bh + (size_t)n0 * CDIM, Bl + (size_t)n0 * CDIM };

    float acc[4][4][4];
    #pragma unroll
    for (int a = 0; a < 4; a++)
        #pragma unroll
        for (int b = 0; b < 4; b++)
            #pragma unroll
            for (int c = 0; c < 4; c++) acc[a][b][c] = 0.f;

    auto load_stage = [&](int chunk, int stage) {
        const int k0 = chunk * 64;
        #pragma unroll
        for (int t = 0; t < 4; t++) {
            const __nv_bfloat16* g = gsrc[t];
            const uint32_t sbase = sb + stage * STAGE_B + t * TILE_B;
            #pragma unroll
            for (int j = 0; j < 4; j++) {
                const int i = tid + j * 256;
                const int r = i >> 3;
                const int c = i & 7;
                const uint32_t soff = sbase + r * 128 + ((c ^ (r & 7)) << 4);
                CP_ASYNC16(soff, g + (size_t)r * CDIM + k0 + c * 8);
            }
        }
        CP_COMMIT();
    };

    load_stage(0, 0);

    #pragma unroll 1
    for (int ch = 0; ch < CDIM / 64; ch++) {
        if (ch + 1 < CDIM / 64) { load_stage(ch + 1, (ch + 1) & 1); CP_WAIT(1); }
        else                    { CP_WAIT(0); }
        __syncthreads();

        const uint32_t st = sb + (ch & 1) * STAGE_B;
        #pragma unroll
        for (int kb = 0; kb < 4; kb++) {
            uint32_t ah[4][4], al[4][4];
            #pragma unroll
            for (int mt = 0; mt < 4; mt++) {
                const int row = wm + mt * 16 + (lane & 15);
                const int col = kb * 2 + (lane >> 4);
                const uint32_t off = row * 128 + ((col ^ (row & 7)) << 4);
                LDSM_X4(ah[mt][0], ah[mt][1], ah[mt][2], ah[mt][3], st + 0 * TILE_B + off);
                LDSM_X4(al[mt][0], al[mt][1], al[mt][2], al[mt][3], st + 1 * TILE_B + off);
            }
            uint32_t bh[2][4], bl[2][4];
            #pragma unroll
            for (int nt = 0; nt < 2; nt++) {
                const int row = wn + nt * 16 + (lane & 15);
                const int col = kb * 2 + (lane >> 4);
                const uint32_t off = row * 128 + ((col ^ (row & 7)) << 4);
                LDSM_X4(bh[nt][0], bh[nt][1], bh[nt][2], bh[nt][3], st + 2 * TILE_B + off);
                LDSM_X4(bl[nt][0], bl[nt][1], bl[nt][2], bl[nt][3], st + 3 * TILE_B + off);
            }
            #pragma unroll
            for (int mt = 0; mt < 4; mt++) {
                #pragma unroll
                for (int n8 = 0; n8 < 4; n8++) {
                    const int t2 = n8 >> 1, s2 = n8 & 1;
                    MMA_BF16(acc[mt][n8], ah[mt], bh[t2][s2], bh[t2][s2 + 2]);
                    MMA_BF16(acc[mt][n8], ah[mt], bl[t2][s2], bl[t2][s2 + 2]);
                    MMA_BF16(acc[mt][n8], al[mt], bh[t2][s2], bh[t2][s2 + 2]);
                }
            }
        }
        __syncthreads();
    }

    // Epilogue
    const int quad = lane >> 2;
    const int tq   = (lane & 3) * 2;
    #pragma unroll
    for (int mt = 0; mt < 4; mt++) {
        #pragma unroll
        for (int n8 = 0; n8 < 4; n8++) {
            const int col = n0 + wn + n8 * 8 + tq;
            const int row = m0 + wm + mt * 16 + quad;
            float b0 = bias[col], b1 = bias[col + 1];
            if (QKV) {
                const int tsel = col / CDIM;             // 0=q 1=k 2=v
                const int hd = col % CDIM;
                const int hh = hd >> 6, d = hd & 63;
                float z0 = zeta[hd], z1 = zeta[hd + 1];
                float v0 = (acc[mt][n8][0] + b0) * z0;
                float v1 = (acc[mt][n8][1] + b1) * z1;
                float v2 = (acc[mt][n8][2] + b0) * z0;
                float v3 = (acc[mt][n8][3] + b1) * z1;
                if (tsel == 0) { v0 *= 0.125f; v1 *= 0.125f; v2 *= 0.125f; v3 *= 0.125f; }
                __nv_bfloat16* dh = (tsel == 0) ? g_qh : (tsel == 1) ? g_kh : g_vh;
                __nv_bfloat16* dl = (tsel == 0) ? g_ql : (tsel == 1) ? g_kl : g_vl;
                const int b = row >> 10, n = row & 1023;
                const size_t idx = (((size_t)(b * HEADS + hh)) << 16) + (size_t)n * 64 + d;
                uint32_t h01, l01, h23, l23;
                split2(v0, v1, h01, l01);
                split2(v2, v3, h23, l23);
                *(uint32_t*)(dh + idx)            = h01;
                *(uint32_t*)(dl + idx)            = l01;
                *(uint32_t*)(dh + idx + 8 * 64)   = h23;
                *(uint32_t*)(dl + idx + 8 * 64)   = l23;
            } else {
                float2 v0 = { acc[mt][n8][0] + b0, acc[mt][n8][1] + b1 };
                float2 v1 = { acc[mt][n8][2] + b0, acc[mt][n8][3] + b1 };
                *(float2*)(Cout + (size_t)row * N + col)       = v0;
                *(float2*)(Cout + (size_t)(row + 8) * N + col) = v1;
            }
        }
    }
}

// ---------------------------------------------------------------------------
// Flash attention on mma.sync, split-bf16 (3-product) for QK^T and PV.
// CTA: 128 q-rows of one (b,h); 8 warps x 16 rows; 64-key tiles, double buffer.
// ---------------------------------------------------------------------------
#define AT_SMEM (32768 + 65536 + 1024)

__global__ void __launch_bounds__(256, 1)
attn_hmma_kernel(const unsigned char* __restrict__ mask)
{
    extern __shared__ char sm[];
    const uint32_t sb = smem_u32(sm);
    const uint32_t stage_s = sb + 32768;          // 2 x 32KB (Kh|Kl|Vh|Vl, 8KB each)
    unsigned char* msk = (unsigned char*)(sm + 98304);

    const int tid = threadIdx.x, lane = tid & 31, wid = tid >> 5;
    const int qt = blockIdx.x, h = blockIdx.y, b = blockIdx.z;
    const int m0 = qt * 128;
    const size_t head_off = ((size_t)(b * HEADS + h)) << 16;   // *SEQ*HDIM

    // stage-0 K/V prefetch
    auto load_kv = [&](int t, int s) {
        const uint32_t base = stage_s + s * 32768;
        const size_t ko = head_off + (size_t)(t * 64) * 64;
        const __nv_bfloat16* srcs[4] = { g_kh + ko, g_kl + ko, g_vh + ko, g_vl + ko };
        #pragma unroll
        for (int tt = 0; tt < 4; tt++) {
            #pragma unroll
            for (int j = 0; j < 2; j++) {
                const int i = tid + j * 256;
                const int r = i >> 3, c = i & 7;
                const uint32_t soff = base + tt * 8192 + r * 128 + ((c ^ (r & 7)) << 4);
                CP_ASYNC16(soff, srcs[tt] + (size_t)r * 64 + c * 8);
            }
        }
        CP_COMMIT();
    };
    load_kv(0, 0);

    // mask to smem (+ global any-mask flag)
    const uint32_t mw = ((const uint32_t*)(mask + b * SEQ))[tid];
    ((uint32_t*)msk)[tid] = mw;

    // Q tile (hi/lo) to smem, swizzled
    {
        const __nv_bfloat16* qsh = g_qh + head_off + (size_t)m0 * 64;
        const __nv_bfloat16* qsl = g_ql + head_off + (size_t)m0 * 64;
        #pragma unroll
        for (int j = 0; j < 4; j++) {
            const int i = tid + j * 256;
            const int r = i >> 3, c = i & 7;
            const uint32_t sw = r * 128 + ((c ^ (r & 7)) << 4);
            *(uint4*)(sm + sw)         = *(const uint4*)(qsh + (size_t)r * 64 + c * 8);
            *(uint4*)(sm + 16384 + sw) = *(const uint4*)(qsl + (size_t)r * 64 + c * 8);
        }
    }
    const int anymask = __syncthreads_or(mw != 0);

    // Q fragments
    uint32_t qfh[4][4], qfl[4][4];
    #pragma unroll
    for (int kb = 0; kb < 4; kb++) {
        const int row = wid * 16 + (lane & 15);
        const int col = kb * 2 + (lane >> 4);
        const uint32_t off = row * 128 + ((col ^ (row & 7)) << 4);
        LDSM_X4(qfh[kb][0], qfh[kb][1], qfh[kb][2], qfh[kb][3], sb + off);
        LDSM_X4(qfl[kb][0], qfl[kb][1], qfl[kb][2], qfl[kb][3], sb + 16384 + off);
    }

    float mrow0 = -1e30f, mrow1 = -1e30f, lrow0 = 0.f, lrow1 = 0.f;
    float oa[8][4];
    #pragma unroll
    for (int i = 0; i < 8; i++)
        #pragma unroll
        for (int j = 0; j < 4; j++) oa[i][j] = 0.f;

    #pragma unroll 1
    for (int t = 0; t < 16; t++) {
        if (t < 15) { load_kv(t + 1, (t + 1) & 1); CP_WAIT(1); }
        else        { CP_WAIT(0); }
        __syncthreads();
        const uint32_t st = stage_s + (t & 1) * 32768;

        // S = Q K^T (3-product split)
        float sa[8][4];
        #pragma unroll
        for (int i = 0; i < 8; i++)
            #pragma unroll
            for (int j = 0; j < 4; j++) sa[i][j] = 0.f;

        #pragma unroll
        for (int kb = 0; kb < 4; kb++) {
            uint32_t kh4[4][4], kl4[4][4];
            #pragma unroll
            for (int kg = 0; kg < 4; kg++) {
                const int row = kg * 16 + (lane & 15);
                const int col = kb * 2 + (lane >> 4);
                const uint32_t off = row * 128 + ((col ^ (row & 7)) << 4);
                LDSM_X4(kh4[kg][0], kh4[kg][1], kh4[kg][2], kh4[kg][3], st + off);
                LDSM_X4(kl4[kg][0], kl4[kg][1], kl4[kg][2], kl4[kg][3], st + 8192 + off);
            }
            #pragma unroll
            for (int kg = 0; kg < 4; kg++)
                #pragma unroll
                for (int s2 = 0; s2 < 2; s2++) {
                    const int n8 = kg * 2 + s2;
                    MMA_BF16(sa[n8], qfh[kb], kh4[kg][s2], kh4[kg][s2 + 2]);
                    MMA_BF16(sa[n8], qfh[kb], kl4[kg][s2], kl4[kg][s2 + 2]);
                    MMA_BF16(sa[n8], qfl[kb], kh4[kg][s2], kh4[kg][s2 + 2]);
                }
        }

        if (anymask) {
            #pragma unroll
            for (int n8 = 0; n8 < 8; n8++) {
                const int k0 = t * 64 + n8 * 8 + (lane & 3) * 2;
                if (msk[k0])     { sa[n8][0] = -3e30f; sa[n8][2] = -3e30f; }
                if (msk[k0 + 1]) { sa[n8][1] = -3e30f; sa[n8][3] = -3e30f; }
            }
        }

        // online softmax
        float t0 = sa[0][0], t1 = sa[0][2];
        #pragma unroll
        for (int n8 = 0; n8 < 8; n8++) {
            t0 = fmaxf(t0, fmaxf(sa[n8][0], sa[n8][1]));
            t1 = fmaxf(t1, fmaxf(sa[n8][2], sa[n8][3]));
        }
        t0 = fmaxf(t0, __shfl_xor_sync(0xFFFFFFFFu, t0, 1));
        t0 = fmaxf(t0, __shfl_xor_sync(0xFFFFFFFFu, t0, 2));
        t1 = fmaxf(t1, __shfl_xor_sync(0xFFFFFFFFu, t1, 1));
        t1 = fmaxf(t1, __shfl_xor_sync(0xFFFFFFFFu, t1, 2));
        const float mn0 = fmaxf(mrow0, t0), mn1 = fmaxf(mrow1, t1);
        const float c0 = __expf(mrow0 - mn0), c1 = __expf(mrow1 - mn1);
        lrow0 *= c0; lrow1 *= c1;
        mrow0 = mn0; mrow1 = mn1;

        uint32_t pha[4][4], pla[4][4];
        #pragma unroll
        for (int n8 = 0; n8 < 8; n8++) {
            const float p0 = __expf(sa[n8][0] - mn0);
            const float p1 = __expf(sa[n8][1] - mn0);
            const float p2 = __expf(sa[n8][2] - mn1);
            const float p3 = __expf(sa[n8][3] - mn1);
            lrow0 += p0 + p1; lrow1 += p2 + p3;
            oa[n8][0] *= c0; oa[n8][1] *= c0; oa[n8][2] *= c1; oa[n8][3] *= c1;
            const int kb = n8 >> 1, hsel = (n8 & 1) * 2;
            uint32_t h01, l01, h23, l23;
            split2(p0, p1, h01, l01);
            split2(p2, p3, h23, l23);
            pha[kb][hsel]     = h01;  pla[kb][hsel]     = l01;
            pha[kb][hsel + 1] = h23;  pla[kb][hsel + 1] = l23;
        }

        // O += P V (3-product split), V via ldmatrix.trans
        #pragma unroll
        for (int kb = 0; kb < 4; kb++) {
            uint32_t vh4[4][4], vl4[4][4];
            #pragma unroll
            for (int g = 0; g < 4; g++) {
                const int ttv = lane >> 3;
                const int key = kb * 16 + (ttv & 1) * 8 + (lane & 7);
                const int c   = 2 * g + (ttv >> 1);
                const uint32_t off = key * 128 + ((c ^ (key & 7)) << 4);
                LDSM_X4_T(vh4[g][0], vh4[g][1], vh4[g][2], vh4[g][3], st + 16384 + off);
                LDSM_X4_T(vl4[g][0], vl4[g][1], vl4[g][2], vl4[g][3], st + 24576 + off);
            }
            #pragma unroll
            for (int g = 0; g < 4; g++)
                #pragma unroll
                for (int s2 = 0; s2 < 2; s2++) {
                    const int n8 = g * 2 + s2;
                    MMA_BF16(oa[n8], pha[kb], vh4[g][2 * s2], vh4[g][2 * s2 + 1]);
                    MMA_BF16(oa[n8], pha[kb], vl4[g][2 * s2], vl4[g][2 * s2 + 1]);
                    MMA_BF16(oa[n8], pla[kb], vh4[g][2 * s2], vh4[g][2 * s2 + 1]);
                }
        }
        __syncthreads();
    }

    // finalize: reduce l across the 4 lanes of each row, normalize, store hi/lo
    lrow0 += __shfl_xor_sync(0xFFFFFFFFu, lrow0, 1);
    lrow0 += __shfl_xor_sync(0xFFFFFFFFu, lrow0, 2);
    lrow1 += __shfl_xor_sync(0xFFFFFFFFu, lrow1, 1);
    lrow1 += __shfl_xor_sync(0xFFFFFFFFu, lrow1, 2);
    const float inv0 = 1.f / lrow0, inv1 = 1.f / lrow1;

    const int r0 = m0 + wid * 16 + (lane >> 2);
    const int cb = h * 64 + (lane & 3) * 2;
    #pragma unroll
    for (int n8 = 0; n8 < 8; n8++) {
        const int col = cb + n8 * 8;
        const size_t i0 = (size_t)(b * SEQ + r0) * CDIM + col;
        const size_t i1 = i0 + (size_t)8 * CDIM;
        uint32_t h01, l01, h23, l23;
        split2(oa[n8][0] * inv0, oa[n8][1] * inv0, h01, l01);
        split2(oa[n8][2] * inv1, oa[n8][3] * inv1, h23, l23);
        *(uint32_t*)(g_ah + i0) = h01;
        *(uint32_t*)(g_al + i0) = l01;
        *(uint32_t*)(g_ah + i1) = h23;
        *(uint32_t*)(g_al + i1) = l23;
    }
}

// ---------------------------------------------------------------------------
// Launch
// ---------------------------------------------------------------------------
extern "C" void kernel_launch(void* const* d_in, const int* in_sizes, int n_in,
                              void* d_out, int out_size)
{
    (void)in_sizes; (void)n_in; (void)out_size;
    const float* x      = (const float*)d_in[0];
    const float* W_qkv  = (const float*)d_in[1];
    const float* b_qkv  = (const float*)d_in[2];
    const float* zeta   = (const float*)d_in[3];
    const float* W_proj = (const float*)d_in[4];
    const float* b_proj = (const float*)d_in[5];
    const unsigned char* mask = (const unsigned char*)d_in[6];
    float* out = (float*)d_out;

    cudaFuncSetAttribute(gemm_hmma_kernel<true>,
                         cudaFuncAttributeMaxDynamicSharedMemorySize, GEMM_SMEM);
    cudaFuncSetAttribute(gemm_hmma_kernel<false>,
                         cudaFuncAttributeMaxDynamicSharedMemorySize, GEMM_SMEM);
    cudaFuncSetAttribute(attn_hmma_kernel,
                         cudaFuncAttributeMaxDynamicSharedMemorySize, AT_SMEM);

    // 1) conversions
    split_x_kernel<<<(MROWS * CDIM / 4 + 255) / 256, 256>>>(x);
    {
        dim3 tb(32, 8);
        wtrans_kernel<true ><<<dim3(QKVC / 32, CDIM / 32), tb>>>(W_qkv);
        wtrans_kernel<false><<<dim3(CDIM / 32, CDIM / 32), tb>>>(W_proj);
    }
    // 2) QKV GEMM -> per-head split q/k/v (q pre-scaled by 0.125)
    gemm_hmma_kernel<true><<<dim3(QKVC / 128, MROWS / 128), 256, GEMM_SMEM>>>(b_qkv, zeta, nullptr);
    // 3) flash attention (HMMA) -> g_ah/g_al
    attn_hmma_kernel<<<dim3(SEQ / 128, HEADS, BATCH), 256, AT_SMEM>>>(mask);
    // 4) projection GEMM -> out
    gemm_hmma_kernel<false><<<dim3(CDIM / 128, MROWS / 128), 256, GEMM_SMEM>>>(b_proj, nullptr, out);
}

// round 8
// speedup vs baseline: 3.0904x; 1.0306x over previous
#include <cuda_runtime.h>
#include <cuda_bf16.h>
#include <math.h>
#include <stdint.h>

// Problem constants
#define BATCH 16
#define SEQ   1024
#define CDIM  768
#define HEADS 12
#define HDIM  64
#define QKVC  2304
#define MROWS 16384

// ---------------------------------------------------------------------------
// Scratch (__device__ globals; allocation-free rule)
// ---------------------------------------------------------------------------
#define HELEMS ((size_t)BATCH * HEADS * SEQ * HDIM)
__device__ __align__(128) __nv_bfloat16 g_xh [(size_t)MROWS * CDIM];
__device__ __align__(128) __nv_bfloat16 g_xl [(size_t)MROWS * CDIM];
__device__ __align__(128) __nv_bfloat16 g_wqh[(size_t)QKVC  * CDIM];
__device__ __align__(128) __nv_bfloat16 g_wql[(size_t)QKVC  * CDIM];
__device__ __align__(128) __nv_bfloat16 g_wph[(size_t)CDIM  * CDIM];
__device__ __align__(128) __nv_bfloat16 g_wpl[(size_t)CDIM  * CDIM];
__device__ __align__(128) __nv_bfloat16 g_qh[HELEMS], g_ql[HELEMS];
__device__ __align__(128) __nv_bfloat16 g_kh[HELEMS], g_kl[HELEMS];
__device__ __align__(128) __nv_bfloat16 g_vh[HELEMS], g_vl[HELEMS];
__device__ __align__(128) __nv_bfloat16 g_ah [(size_t)MROWS * CDIM];
__device__ __align__(128) __nv_bfloat16 g_al [(size_t)MROWS * CDIM];

// ---------------------------------------------------------------------------
// PTX helpers (baseline compute_103 features only)
// ---------------------------------------------------------------------------
__device__ __forceinline__ uint32_t smem_u32(const void* p) {
    uint32_t a;
    asm("{ .reg .u64 t; cvta.to.shared.u64 t, %1; cvt.u32.u64 %0, t; }" : "=r"(a) : "l"(p));
    return a;
}
#define CP_ASYNC16(dst, src) \
    asm volatile("cp.async.cg.shared.global [%0], [%1], 16;" :: "r"(dst), "l"(src))
#define CP_COMMIT() asm volatile("cp.async.commit_group;" ::: "memory")
#define CP_WAIT(n)  asm volatile("cp.async.wait_group %0;" :: "n"(n) : "memory")

#define LDSM_X4(r0, r1, r2, r3, addr) \
    asm volatile("ldmatrix.sync.aligned.m8n8.x4.shared.b16 {%0,%1,%2,%3}, [%4];" \
        : "=r"(r0), "=r"(r1), "=r"(r2), "=r"(r3) : "r"(addr))
#define LDSM_X4_T(r0, r1, r2, r3, addr) \
    asm volatile("ldmatrix.sync.aligned.m8n8.x4.trans.shared.b16 {%0,%1,%2,%3}, [%4];" \
        : "=r"(r0), "=r"(r1), "=r"(r2), "=r"(r3) : "r"(addr))

#define MMA_BF16(d, a, b0r, b1r) \
    asm volatile("mma.sync.aligned.m16n8k16.row.col.f32.bf16.bf16.f32 " \
        "{%0,%1,%2,%3},{%4,%5,%6,%7},{%8,%9},{%0,%1,%2,%3};" \
        : "+f"((d)[0]), "+f"((d)[1]), "+f"((d)[2]), "+f"((d)[3]) \
        : "r"((a)[0]), "r"((a)[1]), "r"((a)[2]), "r"((a)[3]), "r"(b0r), "r"(b1r))

__device__ __forceinline__ void split2(float a, float b, uint32_t& hi, uint32_t& lo) {
    __nv_bfloat16 ah = __float2bfloat16(a), bh = __float2bfloat16(b);
    __nv_bfloat162 h2; h2.x = ah; h2.y = bh;
    __nv_bfloat162 l2;
    l2.x = __float2bfloat16(a - __bfloat162float(ah));
    l2.y = __float2bfloat16(b - __bfloat162float(bh));
    hi = *(uint32_t*)&h2; lo = *(uint32_t*)&l2;
}

// ---------------------------------------------------------------------------
// Conversion kernels
// ---------------------------------------------------------------------------
__global__ void split_x_kernel(const float* __restrict__ x)
{
    int i = blockIdx.x * blockDim.x + threadIdx.x;
    if (i >= MROWS * CDIM / 4) return;
    float4 v = ((const float4*)x)[i];
    float f[4] = {v.x, v.y, v.z, v.w};
    __nv_bfloat16 h[4], l[4];
    #pragma unroll
    for (int j = 0; j < 4; j++) {
        h[j] = __float2bfloat16(f[j]);
        l[j] = __float2bfloat16(f[j] - __bfloat162float(h[j]));
    }
    ((uint2*)g_xh)[i] = *(uint2*)h;
    ((uint2*)g_xl)[i] = *(uint2*)l;
}

template<bool QKV>
__global__ void wtrans_kernel(const float* __restrict__ W)
{
    __shared__ float tile[32][33];
    const int Nd = QKV ? QKVC : CDIM;
    __nv_bfloat16* oh = QKV ? g_wqh : g_wph;
    __nv_bfloat16* ol = QKV ? g_wql : g_wpl;
    const int n0 = blockIdx.x * 32;
    const int k0 = blockIdx.y * 32;
    const int tx = threadIdx.x, ty = threadIdx.y;

    #pragma unroll
    for (int j = 0; j < 4; j++)
        tile[ty + j * 8][tx] = W[(size_t)(k0 + ty + j * 8) * Nd + n0 + tx];
    __syncthreads();
    #pragma unroll
    for (int j = 0; j < 4; j++) {
        const int n = n0 + ty + j * 8;
        const int k = k0 + tx;
        float v = tile[tx][ty + j * 8];
        __nv_bfloat16 h = __float2bfloat16(v);
        oh[(size_t)n * CDIM + k] = h;
        ol[(size_t)n * CDIM + k] = __float2bfloat16(v - __bfloat162float(h));
    }
}

// ---------------------------------------------------------------------------
// HMMA split-bf16 GEMM. 128x128 CTA tile, BK=32, 3-stage cp.async pipeline,
// 2 CTAs/SM. 128x32 tiles folded into 64 rows x 64B halves (SW128, no
// conflicts). 8 warps, warp tile 64x32, 3-product bf16 emulation.
// ---------------------------------------------------------------------------
#define TILE32_B  8192
#define STAGE32_B (4 * TILE32_B)        // Ah|Al|Bh|Bl = 32KB
#define NSTAGE    3
#define GEMM_SMEM (NSTAGE * STAGE32_B)  // 98304

// smem byte offset of (row, 16B-chunk c16) in folded layout; c16 in [0,8)
__device__ __forceinline__ uint32_t fold_off(int row, int c16) {
    return (uint32_t)((row & 63) * 128 + (((((row >> 6) << 2) + c16) ^ (row & 7)) << 4));
}

template<bool QKV>
__global__ void __launch_bounds__(256, 2)
gemm_hmma_kernel(const float* __restrict__ bias,
                 const float* __restrict__ zeta,
                 float* __restrict__ Cout)
{
    const int N = QKV ? QKVC : CDIM;
    const __nv_bfloat16* Ah = QKV ? g_xh  : g_ah;
    const __nv_bfloat16* Al = QKV ? g_xl  : g_al;
    const __nv_bfloat16* Bh = QKV ? g_wqh : g_wph;
    const __nv_bfloat16* Bl = QKV ? g_wql : g_wpl;

    extern __shared__ char smem[];
    const uint32_t sb = smem_u32(smem);
    const int tid  = threadIdx.x;
    const int lane = tid & 31;
    const int wid  = tid >> 5;
    const int wm   = (wid >> 2) * 64;
    const int wn   = (wid & 3) * 32;
    const int m0   = blockIdx.y * 128;
    const int n0   = blockIdx.x * 128;

    const __nv_bfloat16* gsrc[4] = {
        Ah + (size_t)m0 * CDIM, Al + (size_t)m0 * CDIM,
        Bh + (size_t)n0 * CDIM, Bl + (size_t)n0 * CDIM };

    float acc[4][4][4];
    #pragma unroll
    for (int a = 0; a < 4; a++)
        #pragma unroll
        for (int b = 0; b < 4; b++)
            #pragma unroll
            for (int c = 0; c < 4; c++) acc[a][b][c] = 0.f;

    const int nch = CDIM / 32;   // 24

    auto load_stage = [&](int chunk, int stage) {
        const int k0 = chunk * 32;
        #pragma unroll
        for (int t = 0; t < 4; t++) {
            const __nv_bfloat16* g = gsrc[t];
            const uint32_t base = sb + stage * STAGE32_B + t * TILE32_B;
            #pragma unroll
            for (int j = 0; j < 2; j++) {
                const int i = tid + j * 256;     // 0..511
                const int r = i >> 2;            // row 0..127
                const int c = i & 3;             // 16B chunk 0..3
                CP_ASYNC16(base + fold_off(r, c), g + (size_t)r * CDIM + k0 + c * 8);
            }
        }
        CP_COMMIT();
    };

    load_stage(0, 0);
    load_stage(1, 1);

    #pragma unroll 1
    for (int ch = 0; ch < nch; ch++) {
        if (ch + 2 < nch)      { load_stage(ch + 2, (ch + 2) % 3); CP_WAIT(2); }
        else if (ch + 1 < nch) { CP_WAIT(1); }
        else                   { CP_WAIT(0); }
        __syncthreads();

        const uint32_t st = sb + (ch % 3) * STAGE32_B;
        #pragma unroll
        for (int kb = 0; kb < 2; kb++) {
            uint32_t ah[4][4], al[4][4];
            #pragma unroll
            for (int mt = 0; mt < 4; mt++) {
                const int row = wm + mt * 16 + (lane & 15);
                const uint32_t off = fold_off(row, kb * 2 + (lane >> 4));
                LDSM_X4(ah[mt][0], ah[mt][1], ah[mt][2], ah[mt][3], st + 0 * TILE32_B + off);
                LDSM_X4(al[mt][0], al[mt][1], al[mt][2], al[mt][3], st + 1 * TILE32_B + off);
            }
            uint32_t bh[2][4], bl[2][4];
            #pragma unroll
            for (int nt = 0; nt < 2; nt++) {
                const int row = wn + nt * 16 + (lane & 15);
                const uint32_t off = fold_off(row, kb * 2 + (lane >> 4));
                LDSM_X4(bh[nt][0], bh[nt][1], bh[nt][2], bh[nt][3], st + 2 * TILE32_B + off);
                LDSM_X4(bl[nt][0], bl[nt][1], bl[nt][2], bl[nt][3], st + 3 * TILE32_B + off);
            }
            #pragma unroll
            for (int mt = 0; mt < 4; mt++) {
                #pragma unroll
                for (int n8 = 0; n8 < 4; n8++) {
                    const int t2 = n8 >> 1, s2 = n8 & 1;
                    MMA_BF16(acc[mt][n8], ah[mt], bh[t2][s2], bh[t2][s2 + 2]);
                    MMA_BF16(acc[mt][n8], ah[mt], bl[t2][s2], bl[t2][s2 + 2]);
                    MMA_BF16(acc[mt][n8], al[mt], bh[t2][s2], bh[t2][s2 + 2]);
                }
            }
        }
        __syncthreads();
    }

    // Epilogue
    const int quad = lane >> 2;
    const int tq   = (lane & 3) * 2;
    #pragma unroll
    for (int mt = 0; mt < 4; mt++) {
        #pragma unroll
        for (int n8 = 0; n8 < 4; n8++) {
            const int col = n0 + wn + n8 * 8 + tq;
            const int row = m0 + wm + mt * 16 + quad;
            float b0 = bias[col], b1 = bias[col + 1];
            if (QKV) {
                const int tsel = col / CDIM;             // 0=q 1=k 2=v
                const int hd = col % CDIM;
                const int hh = hd >> 6, d = hd & 63;
                float z0 = zeta[hd], z1 = zeta[hd + 1];
                float v0 = (acc[mt][n8][0] + b0) * z0;
                float v1 = (acc[mt][n8][1] + b1) * z1;
                float v2 = (acc[mt][n8][2] + b0) * z0;
                float v3 = (acc[mt][n8][3] + b1) * z1;
                if (tsel == 0) { v0 *= 0.125f; v1 *= 0.125f; v2 *= 0.125f; v3 *= 0.125f; }
                __nv_bfloat16* dh = (tsel == 0) ? g_qh : (tsel == 1) ? g_kh : g_vh;
                __nv_bfloat16* dl = (tsel == 0) ? g_ql : (tsel == 1) ? g_kl : g_vl;
                const int b = row >> 10, n = row & 1023;
                const size_t idx = (((size_t)(b * HEADS + hh)) << 16) + (size_t)n * 64 + d;
                uint32_t h01, l01, h23, l23;
                split2(v0, v1, h01, l01);
                split2(v2, v3, h23, l23);
                *(uint32_t*)(dh + idx)          = h01;
                *(uint32_t*)(dl + idx)          = l01;
                *(uint32_t*)(dh + idx + 8 * 64) = h23;
                *(uint32_t*)(dl + idx + 8 * 64) = l23;
            } else {
                float2 v0 = { acc[mt][n8][0] + b0, acc[mt][n8][1] + b1 };
                float2 v1 = { acc[mt][n8][2] + b0, acc[mt][n8][3] + b1 };
                *(float2*)(Cout + (size_t)row * N + col)       = v0;
                *(float2*)(Cout + (size_t)(row + 8) * N + col) = v1;
            }
        }
    }
}

// ---------------------------------------------------------------------------
// Flash attention on mma.sync, split-bf16 (3-product). 2 CTAs/SM.
// CTA: 128 q-rows of one (b,h); 8 warps x 16 rows; 64-key tiles, dbl buffer.
// ---------------------------------------------------------------------------
#define AT_SMEM (32768 + 65536 + 1024)

__global__ void __launch_bounds__(256, 2)
attn_hmma_kernel(const unsigned char* __restrict__ mask)
{
    extern __shared__ char sm[];
    const uint32_t sb = smem_u32(sm);
    const uint32_t stage_s = sb + 32768;          // 2 x 32KB (Kh|Kl|Vh|Vl, 8KB each)
    unsigned char* msk = (unsigned char*)(sm + 98304);

    const int tid = threadIdx.x, lane = tid & 31, wid = tid >> 5;
    const int qt = blockIdx.x, h = blockIdx.y, b = blockIdx.z;
    const int m0 = qt * 128;
    const size_t head_off = ((size_t)(b * HEADS + h)) << 16;

    auto load_kv = [&](int t, int s) {
        const uint32_t base = stage_s + s * 32768;
        const size_t ko = head_off + (size_t)(t * 64) * 64;
        const __nv_bfloat16* srcs[4] = { g_kh + ko, g_kl + ko, g_vh + ko, g_vl + ko };
        #pragma unroll
        for (int tt = 0; tt < 4; tt++) {
            #pragma unroll
            for (int j = 0; j < 2; j++) {
                const int i = tid + j * 256;
                const int r = i >> 3, c = i & 7;
                const uint32_t soff = base + tt * 8192 + r * 128 + ((c ^ (r & 7)) << 4);
                CP_ASYNC16(soff, srcs[tt] + (size_t)r * 64 + c * 8);
            }
        }
        CP_COMMIT();
    };
    load_kv(0, 0);

    const uint32_t mw = ((const uint32_t*)(mask + b * SEQ))[tid];
    ((uint32_t*)msk)[tid] = mw;

    {
        const __nv_bfloat16* qsh = g_qh + head_off + (size_t)m0 * 64;
        const __nv_bfloat16* qsl = g_ql + head_off + (size_t)m0 * 64;
        #pragma unroll
        for (int j = 0; j < 4; j++) {
            const int i = tid + j * 256;
            const int r = i >> 3, c = i & 7;
            const uint32_t sw = r * 128 + ((c ^ (r & 7)) << 4);
            *(uint4*)(sm + sw)         = *(const uint4*)(qsh + (size_t)r * 64 + c * 8);
            *(uint4*)(sm + 16384 + sw) = *(const uint4*)(qsl + (size_t)r * 64 + c * 8);
        }
    }
    const int anymask = __syncthreads_or(mw != 0);

    // Q-hi fragments cached; Q-lo re-read from smem per use (reg pressure)
    uint32_t qfh[4][4];
    #pragma unroll
    for (int kb = 0; kb < 4; kb++) {
        const int row = wid * 16 + (lane & 15);
        const int col = kb * 2 + (lane >> 4);
        const uint32_t off = row * 128 + ((col ^ (row & 7)) << 4);
        LDSM_X4(qfh[kb][0], qfh[kb][1], qfh[kb][2], qfh[kb][3], sb + off);
    }

    float mrow0 = -1e30f, mrow1 = -1e30f, lrow0 = 0.f, lrow1 = 0.f;
    float oa[8][4];
    #pragma unroll
    for (int i = 0; i < 8; i++)
        #pragma unroll
        for (int j = 0; j < 4; j++) oa[i][j] = 0.f;

    #pragma unroll 1
    for (int t = 0; t < 16; t++) {
        if (t < 15) { load_kv(t + 1, (t + 1) & 1); CP_WAIT(1); }
        else        { CP_WAIT(0); }
        __syncthreads();
        const uint32_t st = stage_s + (t & 1) * 32768;

        // S = Q K^T (3-product split)
        float sa[8][4];
        #pragma unroll
        for (int i = 0; i < 8; i++)
            #pragma unroll
            for (int j = 0; j < 4; j++) sa[i][j] = 0.f;

        #pragma unroll
        for (int kb = 0; kb < 4; kb++) {
            uint32_t kh4[4][4], kl4[4][4];
            #pragma unroll
            for (int kg = 0; kg < 4; kg++) {
                const int row = kg * 16 + (lane & 15);
                const int col = kb * 2 + (lane >> 4);
                const uint32_t off = row * 128 + ((col ^ (row & 7)) << 4);
                LDSM_X4(kh4[kg][0], kh4[kg][1], kh4[kg][2], kh4[kg][3], st + off);
                LDSM_X4(kl4[kg][0], kl4[kg][1], kl4[kg][2], kl4[kg][3], st + 8192 + off);
            }
            uint32_t qfl_t[4];
            {
                const int row = wid * 16 + (lane & 15);
                const int col = kb * 2 + (lane >> 4);
                const uint32_t off = row * 128 + ((col ^ (row & 7)) << 4);
                LDSM_X4(qfl_t[0], qfl_t[1], qfl_t[2], qfl_t[3], sb + 16384 + off);
            }
            #pragma unroll
            for (int kg = 0; kg < 4; kg++)
                #pragma unroll
                for (int s2 = 0; s2 < 2; s2++) {
                    const int n8 = kg * 2 + s2;
                    MMA_BF16(sa[n8], qfh[kb], kh4[kg][s2], kh4[kg][s2 + 2]);
                    MMA_BF16(sa[n8], qfh[kb], kl4[kg][s2], kl4[kg][s2 + 2]);
                    MMA_BF16(sa[n8], qfl_t,   kh4[kg][s2], kh4[kg][s2 + 2]);
                }
        }

        if (anymask) {
            #pragma unroll
            for (int n8 = 0; n8 < 8; n8++) {
                const int k0 = t * 64 + n8 * 8 + (lane & 3) * 2;
                if (msk[k0])     { sa[n8][0] = -3e30f; sa[n8][2] = -3e30f; }
                if (msk[k0 + 1]) { sa[n8][1] = -3e30f; sa[n8][3] = -3e30f; }
            }
        }

        // online softmax; exp overwrites sa in place
        float t0 = sa[0][0], t1 = sa[0][2];
        #pragma unroll
        for (int n8 = 0; n8 < 8; n8++) {
            t0 = fmaxf(t0, fmaxf(sa[n8][0], sa[n8][1]));
            t1 = fmaxf(t1, fmaxf(sa[n8][2], sa[n8][3]));
        }
        t0 = fmaxf(t0, __shfl_xor_sync(0xFFFFFFFFu, t0, 1));
        t0 = fmaxf(t0, __shfl_xor_sync(0xFFFFFFFFu, t0, 2));
        t1 = fmaxf(t1, __shfl_xor_sync(0xFFFFFFFFu, t1, 1));
        t1 = fmaxf(t1, __shfl_xor_sync(0xFFFFFFFFu, t1, 2));
        const float mn0 = fmaxf(mrow0, t0), mn1 = fmaxf(mrow1, t1);
        const float c0 = __expf(mrow0 - mn0), c1 = __expf(mrow1 - mn1);
        lrow0 *= c0; lrow1 *= c1;
        mrow0 = mn0; mrow1 = mn1;

        #pragma unroll
        for (int n8 = 0; n8 < 8; n8++) {
            const float p0 = __expf(sa[n8][0] - mn0);
            const float p1 = __expf(sa[n8][1] - mn0);
            const float p2 = __expf(sa[n8][2] - mn1);
            const float p3 = __expf(sa[n8][3] - mn1);
            lrow0 += p0 + p1; lrow1 += p2 + p3;
            oa[n8][0] *= c0; oa[n8][1] *= c0; oa[n8][2] *= c1; oa[n8][3] *= c1;
            sa[n8][0] = p0; sa[n8][1] = p1; sa[n8][2] = p2; sa[n8][3] = p3;
        }

        // O += P V (3-product split); P split built per key-chunk
        #pragma unroll
        for (int kb = 0; kb < 4; kb++) {
            uint32_t ph[4], pl[4];
            split2(sa[2 * kb][0],     sa[2 * kb][1],     ph[0], pl[0]);
            split2(sa[2 * kb][2],     sa[2 * kb][3],     ph[1], pl[1]);
            split2(sa[2 * kb + 1][0], sa[2 * kb + 1][1], ph[2], pl[2]);
            split2(sa[2 * kb + 1][2], sa[2 * kb + 1][3], ph[3], pl[3]);

            uint32_t vh4[4][4], vl4[4][4];
            #pragma unroll
            for (int g = 0; g < 4; g++) {
                const int ttv = lane >> 3;
                const int key = kb * 16 + (ttv & 1) * 8 + (lane & 7);
                const int c   = 2 * g + (ttv >> 1);
                const uint32_t off = key * 128 + ((c ^ (key & 7)) << 4);
                LDSM_X4_T(vh4[g][0], vh4[g][1], vh4[g][2], vh4[g][3], st + 16384 + off);
                LDSM_X4_T(vl4[g][0], vl4[g][1], vl4[g][2], vl4[g][3], st + 24576 + off);
            }
            #pragma unroll
            for (int g = 0; g < 4; g++)
                #pragma unroll
                for (int s2 = 0; s2 < 2; s2++) {
                    const int n8 = g * 2 + s2;
                    MMA_BF16(oa[n8], ph, vh4[g][2 * s2], vh4[g][2 * s2 + 1]);
                    MMA_BF16(oa[n8], ph, vl4[g][2 * s2], vl4[g][2 * s2 + 1]);
                    MMA_BF16(oa[n8], pl, vh4[g][2 * s2], vh4[g][2 * s2 + 1]);
                }
        }
        __syncthreads();
    }

    lrow0 += __shfl_xor_sync(0xFFFFFFFFu, lrow0, 1);
    lrow0 += __shfl_xor_sync(0xFFFFFFFFu, lrow0, 2);
    lrow1 += __shfl_xor_sync(0xFFFFFFFFu, lrow1, 1);
    lrow1 += __shfl_xor_sync(0xFFFFFFFFu, lrow1, 2);
    const float inv0 = 1.f / lrow0, inv1 = 1.f / lrow1;

    const int r0 = m0 + wid * 16 + (lane >> 2);
    const int cb = h * 64 + (lane & 3) * 2;
    #pragma unroll
    for (int n8 = 0; n8 < 8; n8++) {
        const int col = cb + n8 * 8;
        const size_t i0 = (size_t)(b * SEQ + r0) * CDIM + col;
        const size_t i1 = i0 + (size_t)8 * CDIM;
        uint32_t h01, l01, h23, l23;
        split2(oa[n8][0] * inv0, oa[n8][1] * inv0, h01, l01);
        split2(oa[n8][2] * inv1, oa[n8][3] * inv1, h23, l23);
        *(uint32_t*)(g_ah + i0) = h01;
        *(uint32_t*)(g_al + i0) = l01;
        *(uint32_t*)(g_ah + i1) = h23;
        *(uint32_t*)(g_al + i1) = l23;
    }
}

// ---------------------------------------------------------------------------
// Launch
// ---------------------------------------------------------------------------
extern "C" void kernel_launch(void* const* d_in, const int* in_sizes, int n_in,
                              void* d_out, int out_size)
{
    (void)in_sizes; (void)n_in; (void)out_size;
    const float* x      = (const float*)d_in[0];
    const float* W_qkv  = (const float*)d_in[1];
    const float* b_qkv  = (const float*)d_in[2];
    const float* zeta   = (const float*)d_in[3];
    const float* W_proj = (const float*)d_in[4];
    const float* b_proj = (const float*)d_in[5];
    const unsigned char* mask = (const unsigned char*)d_in[6];
    float* out = (float*)d_out;

    cudaFuncSetAttribute(gemm_hmma_kernel<true>,
                         cudaFuncAttributeMaxDynamicSharedMemorySize, GEMM_SMEM);
    cudaFuncSetAttribute(gemm_hmma_kernel<false>,
                         cudaFuncAttributeMaxDynamicSharedMemorySize, GEMM_SMEM);
    cudaFuncSetAttribute(attn_hmma_kernel,
                         cudaFuncAttributeMaxDynamicSharedMemorySize, AT_SMEM);

    split_x_kernel<<<(MROWS * CDIM / 4 + 255) / 256, 256>>>(x);
    {
        dim3 tb(32, 8);
        wtrans_kernel<true ><<<dim3(QKVC / 32, CDIM / 32), tb>>>(W_qkv);
        wtrans_kernel<false><<<dim3(CDIM / 32, CDIM / 32), tb>>>(W_proj);
    }
    gemm_hmma_kernel<true><<<dim3(QKVC / 128, MROWS / 128), 256, GEMM_SMEM>>>(b_qkv, zeta, nullptr);
    attn_hmma_kernel<<<dim3(SEQ / 128, HEADS, BATCH), 256, AT_SMEM>>>(mask);
    gemm_hmma_kernel<false><<<dim3(CDIM / 128, MROWS / 128), 256, GEMM_SMEM>>>(b_proj, nullptr, out);
}

// round 10
// speedup vs baseline: 3.1415x; 1.0165x over previous
#include <cuda_runtime.h>
#include <cuda_bf16.h>
#include <math.h>
#include <stdint.h>

// Problem constants
#define BATCH 16
#define SEQ   1024
#define CDIM  768
#define HEADS 12
#define HDIM  64
#define QKVC  2304
#define MROWS 16384

// ---------------------------------------------------------------------------
// Scratch (__device__ globals; allocation-free rule)
// ---------------------------------------------------------------------------
#define HELEMS ((size_t)BATCH * HEADS * SEQ * HDIM)
__device__ __align__(128) __nv_bfloat16 g_xh [(size_t)MROWS * CDIM];
__device__ __align__(128) __nv_bfloat16 g_xl [(size_t)MROWS * CDIM];
__device__ __align__(128) __nv_bfloat16 g_wqh[(size_t)QKVC  * CDIM];
__device__ __align__(128) __nv_bfloat16 g_wql[(size_t)QKVC  * CDIM];
__device__ __align__(128) __nv_bfloat16 g_wph[(size_t)CDIM  * CDIM];
__device__ __align__(128) __nv_bfloat16 g_wpl[(size_t)CDIM  * CDIM];
__device__ __align__(128) __nv_bfloat16 g_qh[HELEMS], g_ql[HELEMS];
__device__ __align__(128) __nv_bfloat16 g_kh[HELEMS], g_kl[HELEMS];
__device__ __align__(128) __nv_bfloat16 g_vh[HELEMS], g_vl[HELEMS];
__device__ __align__(128) __nv_bfloat16 g_ah [(size_t)MROWS * CDIM];
__device__ __align__(128) __nv_bfloat16 g_al [(size_t)MROWS * CDIM];

// ---------------------------------------------------------------------------
// PTX helpers (baseline compute_103 features only)
// ---------------------------------------------------------------------------
__device__ __forceinline__ uint32_t smem_u32(const void* p) {
    uint32_t a;
    asm("{ .reg .u64 t; cvta.to.shared.u64 t, %1; cvt.u32.u64 %0, t; }" : "=r"(a) : "l"(p));
    return a;
}
#define CP_ASYNC16(dst, src) \
    asm volatile("cp.async.cg.shared.global [%0], [%1], 16;" :: "r"(dst), "l"(src))
#define CP_COMMIT() asm volatile("cp.async.commit_group;" ::: "memory")
#define CP_WAIT(n)  asm volatile("cp.async.wait_group %0;" :: "n"(n) : "memory")

#define LDSM_X4(r0, r1, r2, r3, addr) \
    asm volatile("ldmatrix.sync.aligned.m8n8.x4.shared.b16 {%0,%1,%2,%3}, [%4];" \
        : "=r"(r0), "=r"(r1), "=r"(r2), "=r"(r3) : "r"(addr))
#define LDSM_X4_T(r0, r1, r2, r3, addr) \
    asm volatile("ldmatrix.sync.aligned.m8n8.x4.trans.shared.b16 {%0,%1,%2,%3}, [%4];" \
        : "=r"(r0), "=r"(r1), "=r"(r2), "=r"(r3) : "r"(addr))

#define MMA_BF16(d, a, b0r, b1r) \
    asm volatile("mma.sync.aligned.m16n8k16.row.col.f32.bf16.bf16.f32 " \
        "{%0,%1,%2,%3},{%4,%5,%6,%7},{%8,%9},{%0,%1,%2,%3};" \
        : "+f"((d)[0]), "+f"((d)[1]), "+f"((d)[2]), "+f"((d)[3]) \
        : "r"((a)[0]), "r"((a)[1]), "r"((a)[2]), "r"((a)[3]), "r"(b0r), "r"(b1r))

__device__ __forceinline__ void split2(float a, float b, uint32_t& hi, uint32_t& lo) {
    __nv_bfloat16 ah = __float2bfloat16(a), bh = __float2bfloat16(b);
    __nv_bfloat162 h2; h2.x = ah; h2.y = bh;
    __nv_bfloat162 l2;
    l2.x = __float2bfloat16(a - __bfloat162float(ah));
    l2.y = __float2bfloat16(b - __bfloat162float(bh));
    hi = *(uint32_t*)&h2; lo = *(uint32_t*)&l2;
}

// ---------------------------------------------------------------------------
// Conversion kernels
// ---------------------------------------------------------------------------
__global__ void split_x_kernel(const float* __restrict__ x)
{
    int i = blockIdx.x * blockDim.x + threadIdx.x;
    if (i >= MROWS * CDIM / 4) return;
    float4 v = ((const float4*)x)[i];
    float f[4] = {v.x, v.y, v.z, v.w};
    __nv_bfloat16 h[4], l[4];
    #pragma unroll
    for (int j = 0; j < 4; j++) {
        h[j] = __float2bfloat16(f[j]);
        l[j] = __float2bfloat16(f[j] - __bfloat162float(h[j]));
    }
    ((uint2*)g_xh)[i] = *(uint2*)h;
    ((uint2*)g_xl)[i] = *(uint2*)l;
}

template<bool QKV>
__global__ void wtrans_kernel(const float* __restrict__ W)
{
    __shared__ float tile[32][33];
    const int Nd = QKV ? QKVC : CDIM;
    __nv_bfloat16* oh = QKV ? g_wqh : g_wph;
    __nv_bfloat16* ol = QKV ? g_wql : g_wpl;
    const int n0 = blockIdx.x * 32;
    const int k0 = blockIdx.y * 32;
    const int tx = threadIdx.x, ty = threadIdx.y;

    #pragma unroll
    for (int j = 0; j < 4; j++)
        tile[ty + j * 8][tx] = W[(size_t)(k0 + ty + j * 8) * Nd + n0 + tx];
    __syncthreads();
    #pragma unroll
    for (int j = 0; j < 4; j++) {
        const int n = n0 + ty + j * 8;
        const int k = k0 + tx;
        float v = tile[tx][ty + j * 8];
        __nv_bfloat16 h = __float2bfloat16(v);
        oh[(size_t)n * CDIM + k] = h;
        ol[(size_t)n * CDIM + k] = __float2bfloat16(v - __bfloat162float(h));
    }
}

// ---------------------------------------------------------------------------
// HMMA split-bf16 GEMM. 128x128 CTA tile, BK=32, 3-stage cp.async,
// 128 threads (4 warps, 64x64 warp tile), 2 CTAs/SM, ONE barrier per chunk.
// ---------------------------------------------------------------------------
#define TILE32_B  8192
#define STAGE32_B (4 * TILE32_B)        // Ah|Al|Bh|Bl = 32KB
#define GEMM_SMEM (3 * STAGE32_B)       // 98304

// smem byte offset of (row, 16B-chunk c16) in folded layout; c16 in [0,8)
__device__ __forceinline__ uint32_t fold_off(int row, int c16) {
    return (uint32_t)((row & 63) * 128 + (((((row >> 6) << 2) + c16) ^ (row & 7)) << 4));
}

template<bool QKV>
__global__ void __launch_bounds__(128, 2)
gemm_hmma_kernel(const float* __restrict__ bias,
                 const float* __restrict__ zeta,
                 float* __restrict__ Cout)
{
    const int N = QKV ? QKVC : CDIM;
    const __nv_bfloat16* Ah = QKV ? g_xh  : g_ah;
    const __nv_bfloat16* Al = QKV ? g_xl  : g_al;
    const __nv_bfloat16* Bh = QKV ? g_wqh : g_wph;
    const __nv_bfloat16* Bl = QKV ? g_wql : g_wpl;

    extern __shared__ char smem[];
    const uint32_t sb = smem_u32(smem);
    const int tid  = threadIdx.x;
    const int lane = tid & 31;
    const int wid  = tid >> 5;           // 0..3
    const int wm   = (wid >> 1) * 64;    // 0 / 64
    const int wn   = (wid & 1) * 64;     // 0 / 64
    const int m0   = blockIdx.y * 128;
    const int n0   = blockIdx.x * 128;

    const __nv_bfloat16* gsrc[4] = {
        Ah + (size_t)m0 * CDIM, Al + (size_t)m0 * CDIM,
        Bh + (size_t)n0 * CDIM, Bl + (size_t)n0 * CDIM };

    float acc[4][8][4];
    #pragma unroll
    for (int a = 0; a < 4; a++)
        #pragma unroll
        for (int b = 0; b < 8; b++)
            #pragma unroll
            for (int c = 0; c < 4; c++) acc[a][b][c] = 0.f;

    const int nch = CDIM / 32;   // 24

    auto load_stage = [&](int chunk, int stage) {
        const int k0 = chunk * 32;
        #pragma unroll
        for (int t = 0; t < 4; t++) {
            const __nv_bfloat16* g = gsrc[t];
            const uint32_t base = sb + stage * STAGE32_B + t * TILE32_B;
            #pragma unroll
            for (int j = 0; j < 4; j++) {
                const int i = tid + j * 128;     // 0..511
                const int r = i >> 2;            // row 0..127
                const int c = i & 3;             // 16B chunk 0..3
                CP_ASYNC16(base + fold_off(r, c), g + (size_t)r * CDIM + k0 + c * 8);
            }
        }
        CP_COMMIT();
    };

    load_stage(0, 0);
    load_stage(1, 1);

    #pragma unroll 1
    for (int ch = 0; ch < nch; ch++) {
        if (ch + 1 < nch) { CP_WAIT(1); }
        else              { CP_WAIT(0); }
        __syncthreads();
        if (ch + 2 < nch) load_stage(ch + 2, (ch + 2) % 3);

        const uint32_t st = sb + (ch % 3) * STAGE32_B;
        #pragma unroll
        for (int kb = 0; kb < 2; kb++) {
            uint32_t ah[4][4], al[4][4];
            #pragma unroll
            for (int mt = 0; mt < 4; mt++) {
                const int row = wm + mt * 16 + (lane & 15);
                const uint32_t off = fold_off(row, kb * 2 + (lane >> 4));
                LDSM_X4(ah[mt][0], ah[mt][1], ah[mt][2], ah[mt][3], st + 0 * TILE32_B + off);
                LDSM_X4(al[mt][0], al[mt][1], al[mt][2], al[mt][3], st + 1 * TILE32_B + off);
            }
            uint32_t bh[4][4], bl[4][4];
            #pragma unroll
            for (int nt = 0; nt < 4; nt++) {
                const int row = wn + nt * 16 + (lane & 15);
                const uint32_t off = fold_off(row, kb * 2 + (lane >> 4));
                LDSM_X4(bh[nt][0], bh[nt][1], bh[nt][2], bh[nt][3], st + 2 * TILE32_B + off);
                LDSM_X4(bl[nt][0], bl[nt][1], bl[nt][2], bl[nt][3], st + 3 * TILE32_B + off);
            }
            #pragma unroll
            for (int mt = 0; mt < 4; mt++) {
                #pragma unroll
                for (int n8 = 0; n8 < 8; n8++) {
                    const int nt = n8 >> 1, s2 = n8 & 1;
                    MMA_BF16(acc[mt][n8], ah[mt], bh[nt][s2], bh[nt][s2 + 2]);
                    MMA_BF16(acc[mt][n8], ah[mt], bl[nt][s2], bl[nt][s2 + 2]);
                    MMA_BF16(acc[mt][n8], al[mt], bh[nt][s2], bh[nt][s2 + 2]);
                }
            }
        }
    }

    // Epilogue
    const int quad = lane >> 2;
    const int tq   = (lane & 3) * 2;
    #pragma unroll
    for (int mt = 0; mt < 4; mt++) {
        #pragma unroll
        for (int n8 = 0; n8 < 8; n8++) {
            const int col = n0 + wn + n8 * 8 + tq;
            const int row = m0 + wm + mt * 16 + quad;
            float b0 = bias[col], b1 = bias[col + 1];
            if (QKV) {
                const int tsel = col / CDIM;             // 0=q 1=k 2=v
                const int hd = col % CDIM;
                const int hh = hd >> 6, d = hd & 63;
                float z0 = zeta[hd], z1 = zeta[hd + 1];
                float v0 = (acc[mt][n8][0] + b0) * z0;
                float v1 = (acc[mt][n8][1] + b1) * z1;
                float v2 = (acc[mt][n8][2] + b0) * z0;
                float v3 = (acc[mt][n8][3] + b1) * z1;
                if (tsel == 0) { v0 *= 0.125f; v1 *= 0.125f; v2 *= 0.125f; v3 *= 0.125f; }
                __nv_bfloat16* dh = (tsel == 0) ? g_qh : (tsel == 1) ? g_kh : g_vh;
                __nv_bfloat16* dl = (tsel == 0) ? g_ql : (tsel == 1) ? g_kl : g_vl;
                const int b = row >> 10, n = row & 1023;
                const size_t idx = (((size_t)(b * HEADS + hh)) << 16) + (size_t)n * 64 + d;
                uint32_t h01, l01, h23, l23;
                split2(v0, v1, h01, l01);
                split2(v2, v3, h23, l23);
                *(uint32_t*)(dh + idx)          = h01;
                *(uint32_t*)(dl + idx)          = l01;
                *(uint32_t*)(dh + idx + 8 * 64) = h23;
                *(uint32_t*)(dl + idx + 8 * 64) = l23;
            } else {
                float2 v0 = { acc[mt][n8][0] + b0, acc[mt][n8][1] + b1 };
                float2 v1 = { acc[mt][n8][2] + b0, acc[mt][n8][3] + b1 };
                *(float2*)(Cout + (size_t)row * N + col)       = v0;
                *(float2*)(Cout + (size_t)(row + 8) * N + col) = v1;
            }
        }
    }
}

// ---------------------------------------------------------------------------
// Flash attention on mma.sync, split-bf16 (3-product). 128 threads (4 warps,
// 32 q-rows each), 2 CTAs/SM, ONE barrier per key-chunk, dbl-buffered K/V.
// ---------------------------------------------------------------------------
#define AT_SMEM (32768 + 65536 + 1024)

__global__ void __launch_bounds__(128, 2)
attn_hmma_kernel(const unsigned char* __restrict__ mask)
{
    extern __shared__ char sm[];
    const uint32_t sb = smem_u32(sm);
    const uint32_t stage_s = sb + 32768;          // 2 x 32KB (Kh|Kl|Vh|Vl, 8KB each)
    unsigned char* msk = (unsigned char*)(sm + 98304);

    const int tid = threadIdx.x, lane = tid & 31, wid = tid >> 5;  // wid 0..3
    const int qt = blockIdx.x, h = blockIdx.y, b = blockIdx.z;
    const int m0 = qt * 128;
    const size_t head_off = ((size_t)(b * HEADS + h)) << 16;

    auto load_kv = [&](int t, int s) {
        const uint32_t base = stage_s + s * 32768;
        const size_t ko = head_off + (size_t)(t * 64) * 64;
        const __nv_bfloat16* srcs[4] = { g_kh + ko, g_kl + ko, g_vh + ko, g_vl + ko };
        #pragma unroll
        for (int tt = 0; tt < 4; tt++) {
            #pragma unroll
            for (int j = 0; j < 4; j++) {
                const int i = tid + j * 128;      // 0..511
                const int r = i >> 3, c = i & 7;
                const uint32_t soff = base + tt * 8192 + r * 128 + ((c ^ (r & 7)) << 4);
                CP_ASYNC16(soff, srcs[tt] + (size_t)r * 64 + c * 8);
            }
        }
        CP_COMMIT();
    };
    load_kv(0, 0);

    const uint32_t mw0 = ((const uint32_t*)(mask + b * SEQ))[tid];
    const uint32_t mw1 = ((const uint32_t*)(mask + b * SEQ))[tid + 128];
    ((uint32_t*)msk)[tid]       = mw0;
    ((uint32_t*)msk)[tid + 128] = mw1;

    {
        const __nv_bfloat16* qsh = g_qh + head_off + (size_t)m0 * 64;
        const __nv_bfloat16* qsl = g_ql + head_off + (size_t)m0 * 64;
        #pragma unroll
        for (int j = 0; j < 8; j++) {
            const int i = tid + j * 128;          // 0..1023
            const int r = i >> 3, c = i & 7;
            const uint32_t sw = r * 128 + ((c ^ (r & 7)) << 4);
            *(uint4*)(sm + sw)         = *(const uint4*)(qsh + (size_t)r * 64 + c * 8);
            *(uint4*)(sm + 16384 + sw) = *(const uint4*)(qsl + (size_t)r * 64 + c * 8);
        }
    }
    const int anymask = __syncthreads_or((mw0 | mw1) != 0);

    // Q-hi fragments cached (2 mt x 4 kb); Q-lo re-read from smem per kb
    uint32_t qfh[2][4][4];
    #pragma unroll
    for (int mt = 0; mt < 2; mt++)
        #pragma unroll
        for (int kb = 0; kb < 4; kb++) {
            const int row = wid * 32 + mt * 16 + (lane & 15);
            const int col = kb * 2 + (lane >> 4);
            const uint32_t off = row * 128 + ((col ^ (row & 7)) << 4);
            LDSM_X4(qfh[mt][kb][0], qfh[mt][kb][1], qfh[mt][kb][2], qfh[mt][kb][3], sb + off);
        }

    float mr[2][2], lr[2][2];
    #pragma unroll
    for (int mt = 0; mt < 2; mt++) { mr[mt][0] = mr[mt][1] = -1e30f; lr[mt][0] = lr[mt][1] = 0.f; }
    float oa[2][8][4];
    #pragma unroll
    for (int mt = 0; mt < 2; mt++)
        #pragma unroll
        for (int i = 0; i < 8; i++)
            #pragma unroll
            for (int j = 0; j < 4; j++) oa[mt][i][j] = 0.f;

    #pragma unroll 1
    for (int t = 0; t < 16; t++) {
        CP_WAIT(0);
        __syncthreads();
        if (t < 15) load_kv(t + 1, (t + 1) & 1);
        const uint32_t st = stage_s + (t & 1) * 32768;

        // S = Q K^T (3-product split)
        float sa[2][8][4];
        #pragma unroll
        for (int mt = 0; mt < 2; mt++)
            #pragma unroll
            for (int i = 0; i < 8; i++)
                #pragma unroll
                for (int j = 0; j < 4; j++) sa[mt][i][j] = 0.f;

        #pragma unroll
        for (int kb = 0; kb < 4; kb++) {
            uint32_t kh4[4][4], kl4[4][4];
            #pragma unroll
            for (int kg = 0; kg < 4; kg++) {
                const int row = kg * 16 + (lane & 15);
                const int col = kb * 2 + (lane >> 4);
                const uint32_t off = row * 128 + ((col ^ (row & 7)) << 4);
                LDSM_X4(kh4[kg][0], kh4[kg][1], kh4[kg][2], kh4[kg][3], st + off);
                LDSM_X4(kl4[kg][0], kl4[kg][1], kl4[kg][2], kl4[kg][3], st + 8192 + off);
            }
            uint32_t qfl[2][4];
            #pragma unroll
            for (int mt = 0; mt < 2; mt++) {
                const int row = wid * 32 + mt * 16 + (lane & 15);
                const int col = kb * 2 + (lane >> 4);
                const uint32_t off = row * 128 + ((col ^ (row & 7)) << 4);
                LDSM_X4(qfl[mt][0], qfl[mt][1], qfl[mt][2], qfl[mt][3], sb + 16384 + off);
            }
            #pragma unroll
            for (int mt = 0; mt < 2; mt++)
                #pragma unroll
                for (int kg = 0; kg < 4; kg++)
                    #pragma unroll
                    for (int s2 = 0; s2 < 2; s2++) {
                        const int n8 = kg * 2 + s2;
                        MMA_BF16(sa[mt][n8], qfh[mt][kb], kh4[kg][s2], kh4[kg][s2 + 2]);
                        MMA_BF16(sa[mt][n8], qfh[mt][kb], kl4[kg][s2], kl4[kg][s2 + 2]);
                        MMA_BF16(sa[mt][n8], qfl[mt],     kh4[kg][s2], kh4[kg][s2 + 2]);
                    }
        }

        if (anymask) {
            #pragma unroll
            for (int n8 = 0; n8 < 8; n8++) {
                const int k0 = t * 64 + n8 * 8 + (lane & 3) * 2;
                #pragma unroll
                for (int mt = 0; mt < 2; mt++) {
                    if (msk[k0])     { sa[mt][n8][0] = -3e30f; sa[mt][n8][2] = -3e30f; }
                    if (msk[k0 + 1]) { sa[mt][n8][1] = -3e30f; sa[mt][n8][3] = -3e30f; }
                }
            }
        }

        // online softmax (per mt, two row-halves); exp overwrites sa in place
        float cc[2][2];
        #pragma unroll
        for (int mt = 0; mt < 2; mt++) {
            float t0 = sa[mt][0][0], t1 = sa[mt][0][2];
            #pragma unroll
            for (int n8 = 0; n8 < 8; n8++) {
                t0 = fmaxf(t0, fmaxf(sa[mt][n8][0], sa[mt][n8][1]));
                t1 = fmaxf(t1, fmaxf(sa[mt][n8][2], sa[mt][n8][3]));
            }
            t0 = fmaxf(t0, __shfl_xor_sync(0xFFFFFFFFu, t0, 1));
            t0 = fmaxf(t0, __shfl_xor_sync(0xFFFFFFFFu, t0, 2));
            t1 = fmaxf(t1, __shfl_xor_sync(0xFFFFFFFFu, t1, 1));
            t1 = fmaxf(t1, __shfl_xor_sync(0xFFFFFFFFu, t1, 2));
            const float mn0 = fmaxf(mr[mt][0], t0), mn1 = fmaxf(mr[mt][1], t1);
            const float c0 = __expf(mr[mt][0] - mn0), c1 = __expf(mr[mt][1] - mn1);
            lr[mt][0] *= c0; lr[mt][1] *= c1;
            mr[mt][0] = mn0; mr[mt][1] = mn1;
            cc[mt][0] = c0;  cc[mt][1] = c1;

            #pragma unroll
            for (int n8 = 0; n8 < 8; n8++) {
                const float p0 = __expf(sa[mt][n8][0] - mn0);
                const float p1 = __expf(sa[mt][n8][1] - mn0);
                const float p2 = __expf(sa[mt][n8][2] - mn1);
                const float p3 = __expf(sa[mt][n8][3] - mn1);
                lr[mt][0] += p0 + p1; lr[mt][1] += p2 + p3;
                oa[mt][n8][0] *= c0; oa[mt][n8][1] *= c0;
                oa[mt][n8][2] *= c1; oa[mt][n8][3] *= c1;
                sa[mt][n8][0] = p0; sa[mt][n8][1] = p1;
                sa[mt][n8][2] = p2; sa[mt][n8][3] = p3;
            }
        }

        // O += P V (3-product split); P split built per key-chunk
        #pragma unroll
        for (int kb = 0; kb < 4; kb++) {
            uint32_t ph[2][4], pl[2][4];
            #pragma unroll
            for (int mt = 0; mt < 2; mt++) {
                split2(sa[mt][2 * kb][0],     sa[mt][2 * kb][1],     ph[mt][0], pl[mt][0]);
                split2(sa[mt][2 * kb][2],     sa[mt][2 * kb][3],     ph[mt][1], pl[mt][1]);
                split2(sa[mt][2 * kb + 1][0], sa[mt][2 * kb + 1][1], ph[mt][2], pl[mt][2]);
                split2(sa[mt][2 * kb + 1][2], sa[mt][2 * kb + 1][3], ph[mt][3], pl[mt][3]);
            }
            uint32_t vh4[4][4], vl4[4][4];
            #pragma unroll
            for (int g = 0; g < 4; g++) {
                const int ttv = lane >> 3;
                const int key = kb * 16 + (ttv & 1) * 8 + (lane & 7);
                const int c   = 2 * g + (ttv >> 1);
                const uint32_t off = key * 128 + ((c ^ (key & 7)) << 4);
                LDSM_X4_T(vh4[g][0], vh4[g][1], vh4[g][2], vh4[g][3], st + 16384 + off);
                LDSM_X4_T(vl4[g][0], vl4[g][1], vl4[g][2], vl4[g][3], st + 24576 + off);
            }
            #pragma unroll
            for (int mt = 0; mt < 2; mt++)
                #pragma unroll
                for (int g = 0; g < 4; g++)
                    #pragma unroll
                    for (int s2 = 0; s2 < 2; s2++) {
                        const int n8 = g * 2 + s2;
                        MMA_BF16(oa[mt][n8], ph[mt], vh4[g][2 * s2], vh4[g][2 * s2 + 1]);
                        MMA_BF16(oa[mt][n8], ph[mt], vl4[g][2 * s2], vl4[g][2 * s2 + 1]);
                        MMA_BF16(oa[mt][n8], pl[mt], vh4[g][2 * s2], vh4[g][2 * s2 + 1]);
                    }
        }
    }

    // finalize: reduce l, normalize, store hi/lo
    #pragma unroll
    for (int mt = 0; mt < 2; mt++) {
        lr[mt][0] += __shfl_xor_sync(0xFFFFFFFFu, lr[mt][0], 1);
        lr[mt][0] += __shfl_xor_sync(0xFFFFFFFFu, lr[mt][0], 2);
        lr[mt][1] += __shfl_xor_sync(0xFFFFFFFFu, lr[mt][1], 1);
        lr[mt][1] += __shfl_xor_sync(0xFFFFFFFFu, lr[mt][1], 2);
        const float inv0 = 1.f / lr[mt][0], inv1 = 1.f / lr[mt][1];

        const int r0 = m0 + wid * 32 + mt * 16 + (lane >> 2);
        const int cb = h * 64 + (lane & 3) * 2;
        #pragma unroll
        for (int n8 = 0; n8 < 8; n8++) {
            const int col = cb + n8 * 8;
            const size_t i0 = (size_t)(b * SEQ + r0) * CDIM + col;
            const size_t i1 = i0 + (size_t)8 * CDIM;
            uint32_t h01, l01, h23, l23;
            split2(oa[mt][n8][0] * inv0, oa[mt][n8][1] * inv0, h01, l01);
            split2(oa[mt][n8][2] * inv1, oa[mt][n8][3] * inv1, h23, l23);
            *(uint32_t*)(g_ah + i0) = h01;
            *(uint32_t*)(g_al + i0) = l01;
            *(uint32_t*)(g_ah + i1) = h23;
            *(uint32_t*)(g_al + i1) = l23;
        }
    }
}

// ---------------------------------------------------------------------------
// Launch
// ---------------------------------------------------------------------------
extern "C" void kernel_launch(void* const* d_in, const int* in_sizes, int n_in,
                              void* d_out, int out_size)
{
    (void)in_sizes; (void)n_in; (void)out_size;
    const float* x      = (const float*)d_in[0];
    const float* W_qkv  = (const float*)d_in[1];
    const float* b_qkv  = (const float*)d_in[2];
    const float* zeta   = (const float*)d_in[3];
    const float* W_proj = (const float*)d_in[4];
    const float* b_proj = (const float*)d_in[5];
    const unsigned char* mask = (const unsigned char*)d_in[6];
    float* out = (float*)d_out;

    cudaFuncSetAttribute(gemm_hmma_kernel<true>,
                         cudaFuncAttributeMaxDynamicSharedMemorySize, GEMM_SMEM);
    cudaFuncSetAttribute(gemm_hmma_kernel<false>,
                         cudaFuncAttributeMaxDynamicSharedMemorySize, GEMM_SMEM);
    cudaFuncSetAttribute(attn_hmma_kernel,
                         cudaFuncAttributeMaxDynamicSharedMemorySize, AT_SMEM);

    split_x_kernel<<<(MROWS * CDIM / 4 + 255) / 256, 256>>>(x);
    {
        dim3 tb(32, 8);
        wtrans_kernel<true ><<<dim3(QKVC / 32, CDIM / 32), tb>>>(W_qkv);
        wtrans_kernel<false><<<dim3(CDIM / 32, CDIM / 32), tb>>>(W_proj);
    }
    gemm_hmma_kernel<true><<<dim3(QKVC / 128, MROWS / 128), 128, GEMM_SMEM>>>(b_qkv, zeta, nullptr);
    attn_hmma_kernel<<<dim3(SEQ / 128, HEADS, BATCH), 128, AT_SMEM>>>(mask);
    gemm_hmma_kernel<false><<<dim3(CDIM / 128, MROWS / 128), 128, GEMM_SMEM>>>(b_proj, nullptr, out);
}

// round 11
// speedup vs baseline: 7.7681x; 2.4727x over previous
#include <cuda_runtime.h>
#include <cuda_fp16.h>
#include <math.h>
#include <stdint.h>

// Problem constants
#define BATCH 16
#define SEQ   1024
#define CDIM  768
#define HEADS 12
#define HDIM  64
#define QKVC  2304
#define MROWS 16384

// ---------------------------------------------------------------------------
// Scratch (__device__ globals; allocation-free rule)
// ---------------------------------------------------------------------------
#define HELEMS ((size_t)BATCH * HEADS * SEQ * HDIM)
__device__ __align__(128) __half g_x [(size_t)MROWS * CDIM];    // x fp16
__device__ __align__(128) __half g_wq[(size_t)QKVC  * CDIM];    // W_qkv^T [n][k]
__device__ __align__(128) __half g_wp[(size_t)CDIM  * CDIM];    // W_proj^T [n][k]
__device__ __align__(128) __half g_q[HELEMS];                   // (b,h,n,d) q*0.125
__device__ __align__(128) __half g_k[HELEMS];
__device__ __align__(128) __half g_v[HELEMS];
__device__ __align__(128) __half g_a[(size_t)MROWS * CDIM];     // attn out fp16

// ---------------------------------------------------------------------------
// PTX helpers (baseline compute_103 features only)
// ---------------------------------------------------------------------------
__device__ __forceinline__ uint32_t smem_u32(const void* p) {
    uint32_t a;
    asm("{ .reg .u64 t; cvta.to.shared.u64 t, %1; cvt.u32.u64 %0, t; }" : "=r"(a) : "l"(p));
    return a;
}
#define CP_ASYNC16(dst, src) \
    asm volatile("cp.async.cg.shared.global [%0], [%1], 16;" :: "r"(dst), "l"(src))
#define CP_COMMIT() asm volatile("cp.async.commit_group;" ::: "memory")
#define CP_WAIT(n)  asm volatile("cp.async.wait_group %0;" :: "n"(n) : "memory")

#define LDSM_X4(r0, r1, r2, r3, addr) \
    asm volatile("ldmatrix.sync.aligned.m8n8.x4.shared.b16 {%0,%1,%2,%3}, [%4];" \
        : "=r"(r0), "=r"(r1), "=r"(r2), "=r"(r3) : "r"(addr))
#define LDSM_X4_T(r0, r1, r2, r3, addr) \
    asm volatile("ldmatrix.sync.aligned.m8n8.x4.trans.shared.b16 {%0,%1,%2,%3}, [%4];" \
        : "=r"(r0), "=r"(r1), "=r"(r2), "=r"(r3) : "r"(addr))

#define MMA_F16(d, a, b0r, b1r) \
    asm volatile("mma.sync.aligned.m16n8k16.row.col.f32.f16.f16.f32 " \
        "{%0,%1,%2,%3},{%4,%5,%6,%7},{%8,%9},{%0,%1,%2,%3};" \
        : "+f"((d)[0]), "+f"((d)[1]), "+f"((d)[2]), "+f"((d)[3]) \
        : "r"((a)[0]), "r"((a)[1]), "r"((a)[2]), "r"((a)[3]), "r"(b0r), "r"(b1r))

__device__ __forceinline__ uint32_t pack2h(float a, float b) {
    __half2 h = __floats2half2_rn(a, b);
    return *(uint32_t*)&h;
}

// ---------------------------------------------------------------------------
// Conversion kernels
// ---------------------------------------------------------------------------
__global__ void cvt_x_kernel(const float* __restrict__ x)
{
    int i = blockIdx.x * blockDim.x + threadIdx.x;   // float4 index
    if (i >= MROWS * CDIM / 4) return;
    float4 v = ((const float4*)x)[i];
    uint2 o;
    o.x = pack2h(v.x, v.y);
    o.y = pack2h(v.z, v.w);
    ((uint2*)g_x)[i] = o;
}

// W (768 x Nd fp32, row-major) -> W^T (Nd x 768 fp16), tiled+coalesced
template<bool QKV>
__global__ void wtrans_kernel(const float* __restrict__ W)
{
    __shared__ float tile[32][33];
    const int Nd = QKV ? QKVC : CDIM;
    __half* o = QKV ? g_wq : g_wp;
    const int n0 = blockIdx.x * 32;
    const int k0 = blockIdx.y * 32;
    const int tx = threadIdx.x, ty = threadIdx.y;

    #pragma unroll
    for (int j = 0; j < 4; j++)
        tile[ty + j * 8][tx] = W[(size_t)(k0 + ty + j * 8) * Nd + n0 + tx];
    __syncthreads();
    #pragma unroll
    for (int j = 0; j < 4; j++) {
        const int n = n0 + ty + j * 8;
        const int k = k0 + tx;
        o[(size_t)n * CDIM + k] = __float2half(tile[tx][ty + j * 8]);
    }
}

// ---------------------------------------------------------------------------
// HMMA fp16 GEMM. 128x128 CTA tile, BK=32, 3-stage cp.async, 128 threads
// (4 warps, 64x64 warp tile), one barrier per chunk.
// ---------------------------------------------------------------------------
#define TILE32_B  8192                  // 128x32 fp16, folded 64 rows x 128B
#define STAGE16_B (2 * TILE32_B)        // A|B = 16KB
#define GEMM_SMEM (3 * STAGE16_B)       // 49152

// smem byte offset of (row, 16B-chunk c16) in folded layout; c16 in [0,4)
__device__ __forceinline__ uint32_t fold_off(int row, int c16) {
    return (uint32_t)((row & 63) * 128 + (((((row >> 6) << 2) + c16) ^ (row & 7)) << 4));
}

template<bool QKV>
__global__ void __launch_bounds__(128, 2)
gemm_hmma_kernel(const float* __restrict__ bias,
                 const float* __restrict__ zeta,
                 float* __restrict__ Cout)
{
    const int N = QKV ? QKVC : CDIM;
    const __half* A = QKV ? g_x  : g_a;
    const __half* B = QKV ? g_wq : g_wp;

    extern __shared__ char smem[];
    const uint32_t sb = smem_u32(smem);
    const int tid  = threadIdx.x;
    const int lane = tid & 31;
    const int wid  = tid >> 5;           // 0..3
    const int wm   = (wid >> 1) * 64;    // 0 / 64
    const int wn   = (wid & 1) * 64;     // 0 / 64
    const int m0   = blockIdx.y * 128;
    const int n0   = blockIdx.x * 128;

    const __half* gA = A + (size_t)m0 * CDIM;
    const __half* gB = B + (size_t)n0 * CDIM;

    float acc[4][8][4];
    #pragma unroll
    for (int a = 0; a < 4; a++)
        #pragma unroll
        for (int b = 0; b < 8; b++)
            #pragma unroll
            for (int c = 0; c < 4; c++) acc[a][b][c] = 0.f;

    const int nch = CDIM / 32;   // 24

    auto load_stage = [&](int chunk, int stage) {
        const int k0 = chunk * 32;
        const uint32_t baseA = sb + stage * STAGE16_B;
        const uint32_t baseB = baseA + TILE32_B;
        #pragma unroll
        for (int j = 0; j < 4; j++) {
            const int i = tid + j * 128;     // 0..511
            const int r = i >> 2;            // row 0..127
            const int c = i & 3;             // 16B chunk 0..3
            const uint32_t fo = fold_off(r, c);
            CP_ASYNC16(baseA + fo, gA + (size_t)r * CDIM + k0 + c * 8);
            CP_ASYNC16(baseB + fo, gB + (size_t)r * CDIM + k0 + c * 8);
        }
        CP_COMMIT();
    };

    load_stage(0, 0);
    load_stage(1, 1);

    #pragma unroll 1
    for (int ch = 0; ch < nch; ch++) {
        if (ch + 1 < nch) { CP_WAIT(1); }
        else              { CP_WAIT(0); }
        __syncthreads();
        if (ch + 2 < nch) load_stage(ch + 2, (ch + 2) % 3);

        const uint32_t st = sb + (ch % 3) * STAGE16_B;
        #pragma unroll
        for (int kb = 0; kb < 2; kb++) {
            uint32_t af[4][4];
            #pragma unroll
            for (int mt = 0; mt < 4; mt++) {
                const int row = wm + mt * 16 + (lane & 15);
                const uint32_t off = fold_off(row, kb * 2 + (lane >> 4));
                LDSM_X4(af[mt][0], af[mt][1], af[mt][2], af[mt][3], st + off);
            }
            uint32_t bf[4][4];
            #pragma unroll
            for (int nt = 0; nt < 4; nt++) {
                const int row = wn + nt * 16 + (lane & 15);
                const uint32_t off = fold_off(row, kb * 2 + (lane >> 4));
                LDSM_X4(bf[nt][0], bf[nt][1], bf[nt][2], bf[nt][3], st + TILE32_B + off);
            }
            #pragma unroll
            for (int mt = 0; mt < 4; mt++) {
                #pragma unroll
                for (int n8 = 0; n8 < 8; n8++) {
                    const int nt = n8 >> 1, s2 = n8 & 1;
                    MMA_F16(acc[mt][n8], af[mt], bf[nt][s2], bf[nt][s2 + 2]);
                }
            }
        }
    }

    // Epilogue
    const int quad = lane >> 2;
    const int tq   = (lane & 3) * 2;
    #pragma unroll
    for (int mt = 0; mt < 4; mt++) {
        #pragma unroll
        for (int n8 = 0; n8 < 8; n8++) {
            const int col = n0 + wn + n8 * 8 + tq;
            const int row = m0 + wm + mt * 16 + quad;
            float b0 = bias[col], b1 = bias[col + 1];
            if (QKV) {
                const int tsel = col / CDIM;             // 0=q 1=k 2=v
                const int hd = col % CDIM;
                const int hh = hd >> 6, d = hd & 63;
                float z0 = zeta[hd], z1 = zeta[hd + 1];
                float v0 = (acc[mt][n8][0] + b0) * z0;
                float v1 = (acc[mt][n8][1] + b1) * z1;
                float v2 = (acc[mt][n8][2] + b0) * z0;
                float v3 = (acc[mt][n8][3] + b1) * z1;
                if (tsel == 0) { v0 *= 0.125f; v1 *= 0.125f; v2 *= 0.125f; v3 *= 0.125f; }
                __half* dst = (tsel == 0) ? g_q : (tsel == 1) ? g_k : g_v;
                const int b = row >> 10, n = row & 1023;
                const size_t idx = (((size_t)(b * HEADS + hh)) << 16) + (size_t)n * 64 + d;
                *(uint32_t*)(dst + idx)          = pack2h(v0, v1);
                *(uint32_t*)(dst + idx + 8 * 64) = pack2h(v2, v3);
            } else {
                float2 v0 = { acc[mt][n8][0] + b0, acc[mt][n8][1] + b1 };
                float2 v1 = { acc[mt][n8][2] + b0, acc[mt][n8][3] + b1 };
                *(float2*)(Cout + (size_t)row * N + col)       = v0;
                *(float2*)(Cout + (size_t)(row + 8) * N + col) = v1;
            }
        }
    }
}

// ---------------------------------------------------------------------------
// Flash attention on fp16 mma.sync. 128 threads (4 warps, 32 q-rows each),
// one barrier per key-chunk, double-buffered K/V (16KB/stage).
// ---------------------------------------------------------------------------
#define AT_Q_B    16384                 // 128x64 fp16
#define AT_KV_B   8192                  // 64x64 fp16
#define AT_STAGE  (2 * AT_KV_B)         // K|V = 16KB
#define AT_SMEM   (AT_Q_B + 2 * AT_STAGE + 1024)   // 49152 + 1024

__global__ void __launch_bounds__(128, 2)
attn_hmma_kernel(const unsigned char* __restrict__ mask)
{
    extern __shared__ char sm[];
    const uint32_t sb = smem_u32(sm);
    const uint32_t stage_s = sb + AT_Q_B;
    unsigned char* msk = (unsigned char*)(sm + AT_Q_B + 2 * AT_STAGE);

    const int tid = threadIdx.x, lane = tid & 31, wid = tid >> 5;  // wid 0..3
    const int qt = blockIdx.x, h = blockIdx.y, b = blockIdx.z;
    const int m0 = qt * 128;
    const size_t head_off = ((size_t)(b * HEADS + h)) << 16;

    auto load_kv = [&](int t, int s) {
        const uint32_t base = stage_s + s * AT_STAGE;
        const size_t ko = head_off + (size_t)(t * 64) * 64;
        #pragma unroll
        for (int j = 0; j < 4; j++) {
            const int i = tid + j * 128;      // 0..511
            const int r = i >> 3, c = i & 7;
            const uint32_t soff = base + r * 128 + ((c ^ (r & 7)) << 4);
            CP_ASYNC16(soff,           g_k + ko + (size_t)r * 64 + c * 8);
            CP_ASYNC16(soff + AT_KV_B, g_v + ko + (size_t)r * 64 + c * 8);
        }
        CP_COMMIT();
    };
    load_kv(0, 0);

    const uint32_t mw0 = ((const uint32_t*)(mask + b * SEQ))[tid];
    const uint32_t mw1 = ((const uint32_t*)(mask + b * SEQ))[tid + 128];
    ((uint32_t*)msk)[tid]       = mw0;
    ((uint32_t*)msk)[tid + 128] = mw1;

    {
        const __half* qs = g_q + head_off + (size_t)m0 * 64;
        #pragma unroll
        for (int j = 0; j < 8; j++) {
            const int i = tid + j * 128;      // 0..1023
            const int r = i >> 3, c = i & 7;
            const uint32_t sw = r * 128 + ((c ^ (r & 7)) << 4);
            *(uint4*)(sm + sw) = *(const uint4*)(qs + (size_t)r * 64 + c * 8);
        }
    }
    const int anymask = __syncthreads_or((mw0 | mw1) != 0);

    // Q fragments fully cached (2 mt x 4 kb x 4)
    uint32_t qf[2][4][4];
    #pragma unroll
    for (int mt = 0; mt < 2; mt++)
        #pragma unroll
        for (int kb = 0; kb < 4; kb++) {
            const int row = wid * 32 + mt * 16 + (lane & 15);
            const int col = kb * 2 + (lane >> 4);
            const uint32_t off = row * 128 + ((col ^ (row & 7)) << 4);
            LDSM_X4(qf[mt][kb][0], qf[mt][kb][1], qf[mt][kb][2], qf[mt][kb][3], sb + off);
        }

    float mr[2][2], lr[2][2];
    #pragma unroll
    for (int mt = 0; mt < 2; mt++) { mr[mt][0] = mr[mt][1] = -1e30f; lr[mt][0] = lr[mt][1] = 0.f; }
    float oa[2][8][4];
    #pragma unroll
    for (int mt = 0; mt < 2; mt++)
        #pragma unroll
        for (int i = 0; i < 8; i++)
            #pragma unroll
            for (int j = 0; j < 4; j++) oa[mt][i][j] = 0.f;

    #pragma unroll 1
    for (int t = 0; t < 16; t++) {
        CP_WAIT(0);
        __syncthreads();
        if (t < 15) load_kv(t + 1, (t + 1) & 1);
        const uint32_t st = stage_s + (t & 1) * AT_STAGE;

        // S = Q K^T
        float sa[2][8][4];
        #pragma unroll
        for (int mt = 0; mt < 2; mt++)
            #pragma unroll
            for (int i = 0; i < 8; i++)
                #pragma unroll
                for (int j = 0; j < 4; j++) sa[mt][i][j] = 0.f;

        #pragma unroll
        for (int kb = 0; kb < 4; kb++) {
            uint32_t kf[4][4];
            #pragma unroll
            for (int kg = 0; kg < 4; kg++) {
                const int row = kg * 16 + (lane & 15);
                const int col = kb * 2 + (lane >> 4);
                const uint32_t off = row * 128 + ((col ^ (row & 7)) << 4);
                LDSM_X4(kf[kg][0], kf[kg][1], kf[kg][2], kf[kg][3], st + off);
            }
            #pragma unroll
            for (int mt = 0; mt < 2; mt++)
                #pragma unroll
                for (int kg = 0; kg < 4; kg++)
                    #pragma unroll
                    for (int s2 = 0; s2 < 2; s2++)
                        MMA_F16(sa[mt][kg * 2 + s2], qf[mt][kb], kf[kg][s2], kf[kg][s2 + 2]);
        }

        if (anymask) {
            #pragma unroll
            for (int n8 = 0; n8 < 8; n8++) {
                const int k0 = t * 64 + n8 * 8 + (lane & 3) * 2;
                #pragma unroll
                for (int mt = 0; mt < 2; mt++) {
                    if (msk[k0])     { sa[mt][n8][0] = -3e30f; sa[mt][n8][2] = -3e30f; }
                    if (msk[k0 + 1]) { sa[mt][n8][1] = -3e30f; sa[mt][n8][3] = -3e30f; }
                }
            }
        }

        // online softmax; exp overwrites sa in place
        #pragma unroll
        for (int mt = 0; mt < 2; mt++) {
            float t0 = sa[mt][0][0], t1 = sa[mt][0][2];
            #pragma unroll
            for (int n8 = 0; n8 < 8; n8++) {
                t0 = fmaxf(t0, fmaxf(sa[mt][n8][0], sa[mt][n8][1]));
                t1 = fmaxf(t1, fmaxf(sa[mt][n8][2], sa[mt][n8][3]));
            }
            t0 = fmaxf(t0, __shfl_xor_sync(0xFFFFFFFFu, t0, 1));
            t0 = fmaxf(t0, __shfl_xor_sync(0xFFFFFFFFu, t0, 2));
            t1 = fmaxf(t1, __shfl_xor_sync(0xFFFFFFFFu, t1, 1));
            t1 = fmaxf(t1, __shfl_xor_sync(0xFFFFFFFFu, t1, 2));
            const float mn0 = fmaxf(mr[mt][0], t0), mn1 = fmaxf(mr[mt][1], t1);
            const float c0 = __expf(mr[mt][0] - mn0), c1 = __expf(mr[mt][1] - mn1);
            lr[mt][0] *= c0; lr[mt][1] *= c1;
            mr[mt][0] = mn0; mr[mt][1] = mn1;

            #pragma unroll
            for (int n8 = 0; n8 < 8; n8++) {
                const float p0 = __expf(sa[mt][n8][0] - mn0);
                const float p1 = __expf(sa[mt][n8][1] - mn0);
                const float p2 = __expf(sa[mt][n8][2] - mn1);
                const float p3 = __expf(sa[mt][n8][3] - mn1);
                lr[mt][0] += p0 + p1; lr[mt][1] += p2 + p3;
                oa[mt][n8][0] *= c0; oa[mt][n8][1] *= c0;
                oa[mt][n8][2] *= c1; oa[mt][n8][3] *= c1;
                sa[mt][n8][0] = p0; sa[mt][n8][1] = p1;
                sa[mt][n8][2] = p2; sa[mt][n8][3] = p3;
            }
        }

        // O += P V ; V via ldmatrix.trans
        #pragma unroll
        for (int kb = 0; kb < 4; kb++) {
            uint32_t pf[2][4];
            #pragma unroll
            for (int mt = 0; mt < 2; mt++) {
                pf[mt][0] = pack2h(sa[mt][2 * kb][0],     sa[mt][2 * kb][1]);
                pf[mt][1] = pack2h(sa[mt][2 * kb][2],     sa[mt][2 * kb][3]);
                pf[mt][2] = pack2h(sa[mt][2 * kb + 1][0], sa[mt][2 * kb + 1][1]);
                pf[mt][3] = pack2h(sa[mt][2 * kb + 1][2], sa[mt][2 * kb + 1][3]);
            }
            uint32_t vf[4][4];
            #pragma unroll
            for (int g = 0; g < 4; g++) {
                const int ttv = lane >> 3;
                const int key = kb * 16 + (ttv & 1) * 8 + (lane & 7);
                const int c   = 2 * g + (ttv >> 1);
                const uint32_t off = key * 128 + ((c ^ (key & 7)) << 4);
                LDSM_X4_T(vf[g][0], vf[g][1], vf[g][2], vf[g][3], st + AT_KV_B + off);
            }
            #pragma unroll
            for (int mt = 0; mt < 2; mt++)
                #pragma unroll
                for (int g = 0; g < 4; g++)
                    #pragma unroll
                    for (int s2 = 0; s2 < 2; s2++)
                        MMA_F16(oa[mt][g * 2 + s2], pf[mt], vf[g][2 * s2], vf[g][2 * s2 + 1]);
        }
    }

    // finalize: reduce l, normalize, store fp16
    #pragma unroll
    for (int mt = 0; mt < 2; mt++) {
        lr[mt][0] += __shfl_xor_sync(0xFFFFFFFFu, lr[mt][0], 1);
        lr[mt][0] += __shfl_xor_sync(0xFFFFFFFFu, lr[mt][0], 2);
        lr[mt][1] += __shfl_xor_sync(0xFFFFFFFFu, lr[mt][1], 1);
        lr[mt][1] += __shfl_xor_sync(0xFFFFFFFFu, lr[mt][1], 2);
        const float inv0 = 1.f / lr[mt][0], inv1 = 1.f / lr[mt][1];

        const int r0 = m0 + wid * 32 + mt * 16 + (lane >> 2);
        const int cb = h * 64 + (lane & 3) * 2;
        #pragma unroll
        for (int n8 = 0; n8 < 8; n8++) {
            const int col = cb + n8 * 8;
            const size_t i0 = (size_t)(b * SEQ + r0) * CDIM + col;
            const size_t i1 = i0 + (size_t)8 * CDIM;
            *(uint32_t*)(g_a + i0) = pack2h(oa[mt][n8][0] * inv0, oa[mt][n8][1] * inv0);
            *(uint32_t*)(g_a + i1) = pack2h(oa[mt][n8][2] * inv1, oa[mt][n8][3] * inv1);
        }
    }
}

// ---------------------------------------------------------------------------
// Launch
// ---------------------------------------------------------------------------
extern "C" void kernel_launch(void* const* d_in, const int* in_sizes, int n_in,
                              void* d_out, int out_size)
{
    (void)in_sizes; (void)n_in; (void)out_size;
    const float* x      = (const float*)d_in[0];
    const float* W_qkv  = (const float*)d_in[1];
    const float* b_qkv  = (const float*)d_in[2];
    const float* zeta   = (const float*)d_in[3];
    const float* W_proj = (const float*)d_in[4];
    const float* b_proj = (const float*)d_in[5];
    const unsigned char* mask = (const unsigned char*)d_in[6];
    float* out = (float*)d_out;

    cudaFuncSetAttribute(gemm_hmma_kernel<true>,
                         cudaFuncAttributeMaxDynamicSharedMemorySize, GEMM_SMEM);
    cudaFuncSetAttribute(gemm_hmma_kernel<false>,
                         cudaFuncAttributeMaxDynamicSharedMemorySize, GEMM_SMEM);
    cudaFuncSetAttribute(attn_hmma_kernel,
                         cudaFuncAttributeMaxDynamicSharedMemorySize, AT_SMEM);

    cvt_x_kernel<<<(MROWS * CDIM / 4 + 255) / 256, 256>>>(x);
    {
        dim3 tb(32, 8);
        wtrans_kernel<true ><<<dim3(QKVC / 32, CDIM / 32), tb>>>(W_qkv);
        wtrans_kernel<false><<<dim3(CDIM / 32, CDIM / 32), tb>>>(W_proj);
    }
    gemm_hmma_kernel<true><<<dim3(QKVC / 128, MROWS / 128), 128, GEMM_SMEM>>>(b_qkv, zeta, nullptr);
    attn_hmma_kernel<<<dim3(SEQ / 128, HEADS, BATCH), 128, AT_SMEM>>>(mask);
    gemm_hmma_kernel<false><<<dim3(CDIM / 128, MROWS / 128), 128, GEMM_SMEM>>>(b_proj, nullptr, out);
}

// round 13
// speedup vs baseline: 7.8708x; 1.0132x over previous
#include <cuda_runtime.h>
#include <cuda_fp16.h>
#include <math.h>
#include <stdint.h>

// Problem constants
#define BATCH 16
#define SEQ   1024
#define CDIM  768
#define HEADS 12
#define HDIM  64
#define QKVC  2304
#define MROWS 16384

// ---------------------------------------------------------------------------
// Scratch (__device__ globals; allocation-free rule)
// ---------------------------------------------------------------------------
#define HELEMS ((size_t)BATCH * HEADS * SEQ * HDIM)
__device__ __align__(128) __half g_x [(size_t)MROWS * CDIM];
__device__ __align__(128) __half g_wq[(size_t)QKVC  * CDIM];
__device__ __align__(128) __half g_wp[(size_t)CDIM  * CDIM];
__device__ __align__(128) __half g_q[HELEMS];
__device__ __align__(128) __half g_k[HELEMS];
__device__ __align__(128) __half g_v[HELEMS];
__device__ __align__(128) __half g_a[(size_t)MROWS * CDIM];

// ---------------------------------------------------------------------------
// PTX helpers
// ---------------------------------------------------------------------------
__device__ __forceinline__ uint32_t smem_u32(const void* p) {
    uint32_t a;
    asm("{ .reg .u64 t; cvta.to.shared.u64 t, %1; cvt.u32.u64 %0, t; }" : "=r"(a) : "l"(p));
    return a;
}
#define CP_ASYNC16(dst, src) \
    asm volatile("cp.async.cg.shared.global [%0], [%1], 16;" :: "r"(dst), "l"(src))
#define CP_COMMIT() asm volatile("cp.async.commit_group;" ::: "memory")
#define CP_WAIT(n)  asm volatile("cp.async.wait_group %0;" :: "n"(n) : "memory")

#define LDSM_X4(r0, r1, r2, r3, addr) \
    asm volatile("ldmatrix.sync.aligned.m8n8.x4.shared.b16 {%0,%1,%2,%3}, [%4];" \
        : "=r"(r0), "=r"(r1), "=r"(r2), "=r"(r3) : "r"(addr))
#define LDSM_X4_T(r0, r1, r2, r3, addr) \
    asm volatile("ldmatrix.sync.aligned.m8n8.x4.trans.shared.b16 {%0,%1,%2,%3}, [%4];" \
        : "=r"(r0), "=r"(r1), "=r"(r2), "=r"(r3) : "r"(addr))

#define MMA_F16(d, a, b0r, b1r) \
    asm volatile("mma.sync.aligned.m16n8k16.row.col.f32.f16.f16.f32 " \
        "{%0,%1,%2,%3},{%4,%5,%6,%7},{%8,%9},{%0,%1,%2,%3};" \
        : "+f"((d)[0]), "+f"((d)[1]), "+f"((d)[2]), "+f"((d)[3]) \
        : "r"((a)[0]), "r"((a)[1]), "r"((a)[2]), "r"((a)[3]), "r"(b0r), "r"(b1r))

__device__ __forceinline__ uint32_t pack2h(float a, float b) {
    __half2 h = __floats2half2_rn(a, b);
    return *(uint32_t*)&h;
}

// ---------------------------------------------------------------------------
// Conversion kernels
// ---------------------------------------------------------------------------
__global__ void cvt_x_kernel(const float* __restrict__ x)
{
    int i = blockIdx.x * blockDim.x + threadIdx.x;
    if (i >= MROWS * CDIM / 4) return;
    float4 v = ((const float4*)x)[i];
    uint2 o;
    o.x = pack2h(v.x, v.y);
    o.y = pack2h(v.z, v.w);
    ((uint2*)g_x)[i] = o;
}

template<bool QKV>
__global__ void wtrans_kernel(const float* __restrict__ W)
{
    __shared__ float tile[32][33];
    const int Nd = QKV ? QKVC : CDIM;
    __half* o = QKV ? g_wq : g_wp;
    const int n0 = blockIdx.x * 32;
    const int k0 = blockIdx.y * 32;
    const int tx = threadIdx.x, ty = threadIdx.y;

    #pragma unroll
    for (int j = 0; j < 4; j++)
        tile[ty + j * 8][tx] = W[(size_t)(k0 + ty + j * 8) * Nd + n0 + tx];
    __syncthreads();
    #pragma unroll
    for (int j = 0; j < 4; j++) {
        const int n = n0 + ty + j * 8;
        const int k = k0 + tx;
        o[(size_t)n * CDIM + k] = __float2half(tile[tx][ty + j * 8]);
    }
}

// ---------------------------------------------------------------------------
// HMMA fp16 GEMM. 128x128 CTA tile, BK=32, 3-stage cp.async, 128 threads
// (4 warps, 64x64 warp tile). Whole-chunk fragment preload, precomputed
// swizzle offsets (kb variant = XOR 0x20).
// ---------------------------------------------------------------------------
#define TILE32_B  8192
#define STAGE16_B (2 * TILE32_B)
#define GEMM_SMEM (3 * STAGE16_B)       // 49152

__device__ __forceinline__ uint32_t fold_off(int row, int c16) {
    return (uint32_t)((row & 63) * 128 + (((((row >> 6) << 2) + c16) ^ (row & 7)) << 4));
}

template<bool QKV>
__global__ void __launch_bounds__(128, 2)
gemm_hmma_kernel(const float* __restrict__ bias,
                 const float* __restrict__ zeta,
                 float* __restrict__ Cout)
{
    const int N = QKV ? QKVC : CDIM;
    const __half* A = QKV ? g_x  : g_a;
    const __half* B = QKV ? g_wq : g_wp;

    extern __shared__ char smem[];
    const uint32_t sb = smem_u32(smem);
    const int tid  = threadIdx.x;
    const int lane = tid & 31;
    const int wid  = tid >> 5;
    const int wm   = (wid >> 1) * 64;
    const int wn   = (wid & 1) * 64;
    const int m0   = blockIdx.y * 128;
    const int n0   = blockIdx.x * 128;

    const __half* gA = A + (size_t)m0 * CDIM;
    const __half* gB = B + (size_t)n0 * CDIM;

    // precomputed LDSM offsets (kb=0); kb=1 variant = XOR 0x20
    uint32_t offA[4], offB[4];
    {
        const int r = lane & 15, c = lane >> 4;
        #pragma unroll
        for (int mt = 0; mt < 4; mt++) offA[mt] = fold_off(wm + mt * 16 + r, c);
        #pragma unroll
        for (int nt = 0; nt < 4; nt++) offB[nt] = TILE32_B + fold_off(wn + nt * 16 + r, c);
    }

    float acc[4][8][4];
    #pragma unroll
    for (int a = 0; a < 4; a++)
        #pragma unroll
        for (int b = 0; b < 8; b++)
            #pragma unroll
            for (int c = 0; c < 4; c++) acc[a][b][c] = 0.f;

    const int nch = CDIM / 32;   // 24

    auto load_stage = [&](int chunk, int stage) {
        const int k0 = chunk * 32;
        const uint32_t baseA = sb + stage * STAGE16_B;
        #pragma unroll
        for (int j = 0; j < 4; j++) {
            const int i = tid + j * 128;
            const int r = i >> 2;
            const int c = i & 3;
            const uint32_t fo = fold_off(r, c);
            CP_ASYNC16(baseA + fo,            gA + (size_t)r * CDIM + k0 + c * 8);
            CP_ASYNC16(baseA + TILE32_B + fo, gB + (size_t)r * CDIM + k0 + c * 8);
        }
        CP_COMMIT();
    };

    load_stage(0, 0);
    load_stage(1, 1);

    #pragma unroll 1
    for (int ch = 0; ch < nch; ch++) {
        if (ch + 1 < nch) { CP_WAIT(1); }
        else              { CP_WAIT(0); }
        __syncthreads();
        if (ch + 2 < nch) load_stage(ch + 2, (ch + 2) % 3);

        const uint32_t st = sb + (ch % 3) * STAGE16_B;

        // whole-chunk fragment preload (both kb halves)
        uint32_t af[2][4][4], bf[2][4][4];
        #pragma unroll
        for (int kb = 0; kb < 2; kb++) {
            const uint32_t x = (uint32_t)(kb << 5);
            #pragma unroll
            for (int mt = 0; mt < 4; mt++)
                LDSM_X4(af[kb][mt][0], af[kb][mt][1], af[kb][mt][2], af[kb][mt][3],
                        st + (offA[mt] ^ x));
            #pragma unroll
            for (int nt = 0; nt < 4; nt++)
                LDSM_X4(bf[kb][nt][0], bf[kb][nt][1], bf[kb][nt][2], bf[kb][nt][3],
                        st + (offB[nt] ^ x));
        }
        // uninterrupted MMA stream; dependent kb=1 re-accumulation 64 MMAs later
        #pragma unroll
        for (int kb = 0; kb < 2; kb++)
            #pragma unroll
            for (int mt = 0; mt < 4; mt++)
                #pragma unroll
                for (int n8 = 0; n8 < 8; n8++) {
                    const int nt = n8 >> 1, s2 = n8 & 1;
                    MMA_F16(acc[mt][n8], af[kb][mt], bf[kb][nt][s2], bf[kb][nt][s2 + 2]);
                }
    }

    // Epilogue
    const int quad = lane >> 2;
    const int tq   = (lane & 3) * 2;
    #pragma unroll
    for (int mt = 0; mt < 4; mt++) {
        #pragma unroll
        for (int n8 = 0; n8 < 8; n8++) {
            const int col = n0 + wn + n8 * 8 + tq;
            const int row = m0 + wm + mt * 16 + quad;
            float b0 = bias[col], b1 = bias[col + 1];
            if (QKV) {
                const int tsel = col / CDIM;
                const int hd = col % CDIM;
                const int hh = hd >> 6, d = hd & 63;
                float z0 = zeta[hd], z1 = zeta[hd + 1];
                float v0 = (acc[mt][n8][0] + b0) * z0;
                float v1 = (acc[mt][n8][1] + b1) * z1;
                float v2 = (acc[mt][n8][2] + b0) * z0;
                float v3 = (acc[mt][n8][3] + b1) * z1;
                if (tsel == 0) { v0 *= 0.125f; v1 *= 0.125f; v2 *= 0.125f; v3 *= 0.125f; }
                __half* dst = (tsel == 0) ? g_q : (tsel == 1) ? g_k : g_v;
                const int b = row >> 10, n = row & 1023;
                const size_t idx = (((size_t)(b * HEADS + hh)) << 16) + (size_t)n * 64 + d;
                *(uint32_t*)(dst + idx)          = pack2h(v0, v1);
                *(uint32_t*)(dst + idx + 8 * 64) = pack2h(v2, v3);
            } else {
                float2 v0 = { acc[mt][n8][0] + b0, acc[mt][n8][1] + b1 };
                float2 v1 = { acc[mt][n8][2] + b0, acc[mt][n8][3] + b1 };
                *(float2*)(Cout + (size_t)row * N + col)       = v0;
                *(float2*)(Cout + (size_t)(row + 8) * N + col) = v1;
            }
        }
    }
}

// ---------------------------------------------------------------------------
// Flash attention on fp16 mma.sync. 128 threads (4 warps, 32 q-rows each),
// precomputed swizzle offsets, double-buffered K/V.
// ---------------------------------------------------------------------------
#define AT_Q_B    16384
#define AT_KV_B   8192
#define AT_STAGE  (2 * AT_KV_B)
#define AT_SMEM   (AT_Q_B + 2 * AT_STAGE + 1024)

__global__ void __launch_bounds__(128, 2)
attn_hmma_kernel(const unsigned char* __restrict__ mask)
{
    extern __shared__ char sm[];
    const uint32_t sb = smem_u32(sm);
    const uint32_t stage_s = sb + AT_Q_B;
    unsigned char* msk = (unsigned char*)(sm + AT_Q_B + 2 * AT_STAGE);

    const int tid = threadIdx.x, lane = tid & 31, wid = tid >> 5;
    const int qt = blockIdx.x, h = blockIdx.y, b = blockIdx.z;
    const int m0 = qt * 128;
    const size_t head_off = ((size_t)(b * HEADS + h)) << 16;

    auto load_kv = [&](int t, int s) {
        const uint32_t base = stage_s + s * AT_STAGE;
        const size_t ko = head_off + (size_t)(t * 64) * 64;
        #pragma unroll
        for (int j = 0; j < 4; j++) {
            const int i = tid + j * 128;
            const int r = i >> 3, c = i & 7;
            const uint32_t soff = base + r * 128 + ((c ^ (r & 7)) << 4);
            CP_ASYNC16(soff,           g_k + ko + (size_t)r * 64 + c * 8);
            CP_ASYNC16(soff + AT_KV_B, g_v + ko + (size_t)r * 64 + c * 8);
        }
        CP_COMMIT();
    };
    load_kv(0, 0);

    const uint32_t mw0 = ((const uint32_t*)(mask + b * SEQ))[tid];
    const uint32_t mw1 = ((const uint32_t*)(mask + b * SEQ))[tid + 128];
    ((uint32_t*)msk)[tid]       = mw0;
    ((uint32_t*)msk)[tid + 128] = mw1;

    {
        const __half* qs = g_q + head_off + (size_t)m0 * 64;
        #pragma unroll
        for (int j = 0; j < 8; j++) {
            const int i = tid + j * 128;
            const int r = i >> 3, c = i & 7;
            const uint32_t sw = r * 128 + ((c ^ (r & 7)) << 4);
            *(uint4*)(sm + sw) = *(const uint4*)(qs + (size_t)r * 64 + c * 8);
        }
    }
    const int anymask = __syncthreads_or((mw0 | mw1) != 0);

    // Q fragments fully cached
    uint32_t qf[2][4][4];
    #pragma unroll
    for (int mt = 0; mt < 2; mt++)
        #pragma unroll
        for (int kb = 0; kb < 4; kb++) {
            const int row = wid * 32 + mt * 16 + (lane & 15);
            const int col = kb * 2 + (lane >> 4);
            const uint32_t off = row * 128 + ((col ^ (row & 7)) << 4);
            LDSM_X4(qf[mt][kb][0], qf[mt][kb][1], qf[mt][kb][2], qf[mt][kb][3], sb + off);
        }

    // precomputed K / V offsets (kb=0); K kb variant = XOR (kb<<5), V = +kb*2048
    uint32_t offK[4], offV[4];
    {
        const int r = lane & 15, c = lane >> 4;
        #pragma unroll
        for (int kg = 0; kg < 4; kg++) {
            const int row = kg * 16 + r;
            offK[kg] = row * 128 + ((c ^ (row & 7)) << 4);
        }
        const int ttv = lane >> 3;
        const int key0 = (ttv & 1) * 8 + (lane & 7);
        #pragma unroll
        for (int g = 0; g < 4; g++) {
            const int cc = 2 * g + (ttv >> 1);
            offV[g] = AT_KV_B + key0 * 128 + ((cc ^ (key0 & 7)) << 4);
        }
    }

    float mr[2][2], lr[2][2];
    #pragma unroll
    for (int mt = 0; mt < 2; mt++) { mr[mt][0] = mr[mt][1] = -1e30f; lr[mt][0] = lr[mt][1] = 0.f; }
    float oa[2][8][4];
    #pragma unroll
    for (int mt = 0; mt < 2; mt++)
        #pragma unroll
        for (int i = 0; i < 8; i++)
            #pragma unroll
            for (int j = 0; j < 4; j++) oa[mt][i][j] = 0.f;

    #pragma unroll 1
    for (int t = 0; t < 16; t++) {
        CP_WAIT(0);
        __syncthreads();
        if (t < 15) load_kv(t + 1, (t + 1) & 1);
        const uint32_t st = stage_s + (t & 1) * AT_STAGE;

        // S = Q K^T
        float sa[2][8][4];
        #pragma unroll
        for (int mt = 0; mt < 2; mt++)
            #pragma unroll
            for (int i = 0; i < 8; i++)
                #pragma unroll
                for (int j = 0; j < 4; j++) sa[mt][i][j] = 0.f;

        #pragma unroll
        for (int kb = 0; kb < 4; kb++) {
            const uint32_t x = (uint32_t)(kb << 5);
            uint32_t kf[4][4];
            #pragma unroll
            for (int kg = 0; kg < 4; kg++)
                LDSM_X4(kf[kg][0], kf[kg][1], kf[kg][2], kf[kg][3], st + (offK[kg] ^ x));
            #pragma unroll
            for (int mt = 0; mt < 2; mt++)
                #pragma unroll
                for (int kg = 0; kg < 4; kg++)
                    #pragma unroll
                    for (int s2 = 0; s2 < 2; s2++)
                        MMA_F16(sa[mt][kg * 2 + s2], qf[mt][kb], kf[kg][s2], kf[kg][s2 + 2]);
        }

        if (anymask) {
            #pragma unroll
            for (int n8 = 0; n8 < 8; n8++) {
                const int k0 = t * 64 + n8 * 8 + (lane & 3) * 2;
                #pragma unroll
                for (int mt = 0; mt < 2; mt++) {
                    if (msk[k0])     { sa[mt][n8][0] = -3e30f; sa[mt][n8][2] = -3e30f; }
                    if (msk[k0 + 1]) { sa[mt][n8][1] = -3e30f; sa[mt][n8][3] = -3e30f; }
                }
            }
        }

        // online softmax; exp overwrites sa in place
        #pragma unroll
        for (int mt = 0; mt < 2; mt++) {
            float t0 = sa[mt][0][0], t1 = sa[mt][0][2];
            #pragma unroll
            for (int n8 = 0; n8 < 8; n8++) {
                t0 = fmaxf(t0, fmaxf(sa[mt][n8][0], sa[mt][n8][1]));
                t1 = fmaxf(t1, fmaxf(sa[mt][n8][2], sa[mt][n8][3]));
            }
            t0 = fmaxf(t0, __shfl_xor_sync(0xFFFFFFFFu, t0, 1));
            t0 = fmaxf(t0, __shfl_xor_sync(0xFFFFFFFFu, t0, 2));
            t1 = fmaxf(t1, __shfl_xor_sync(0xFFFFFFFFu, t1, 1));
            t1 = fmaxf(t1, __shfl_xor_sync(0xFFFFFFFFu, t1, 2));
            const float mn0 = fmaxf(mr[mt][0], t0), mn1 = fmaxf(mr[mt][1], t1);
            const float c0 = __expf(mr[mt][0] - mn0), c1 = __expf(mr[mt][1] - mn1);
            lr[mt][0] *= c0; lr[mt][1] *= c1;
            mr[mt][0] = mn0; mr[mt][1] = mn1;

            #pragma unroll
            for (int n8 = 0; n8 < 8; n8++) {
                const float p0 = __expf(sa[mt][n8][0] - mn0);
                const float p1 = __expf(sa[mt][n8][1] - mn0);
                const float p2 = __expf(sa[mt][n8][2] - mn1);
                const float p3 = __expf(sa[mt][n8][3] - mn1);
                lr[mt][0] += p0 + p1; lr[mt][1] += p2 + p3;
                oa[mt][n8][0] *= c0; oa[mt][n8][1] *= c0;
                oa[mt][n8][2] *= c1; oa[mt][n8][3] *= c1;
                sa[mt][n8][0] = p0; sa[mt][n8][1] = p1;
                sa[mt][n8][2] = p2; sa[mt][n8][3] = p3;
            }
        }

        // O += P V ; V via ldmatrix.trans
        #pragma unroll
        for (int kb = 0; kb < 4; kb++) {
            uint32_t pf[2][4];
            #pragma unroll
            for (int mt = 0; mt < 2; mt++) {
                pf[mt][0] = pack2h(sa[mt][2 * kb][0],     sa[mt][2 * kb][1]);
                pf[mt][1] = pack2h(sa[mt][2 * kb][2],     sa[mt][2 * kb][3]);
                pf[mt][2] = pack2h(sa[mt][2 * kb + 1][0], sa[mt][2 * kb + 1][1]);
                pf[mt][3] = pack2h(sa[mt][2 * kb + 1][2], sa[mt][2 * kb + 1][3]);
            }
            uint32_t vf[4][4];
            #pragma unroll
            for (int g = 0; g < 4; g++)
                LDSM_X4_T(vf[g][0], vf[g][1], vf[g][2], vf[g][3],
                          st + offV[g] + kb * 2048);
            #pragma unroll
            for (int mt = 0; mt < 2; mt++)
                #pragma unroll
                for (int g = 0; g < 4; g++)
                    #pragma unroll
                    for (int s2 = 0; s2 < 2; s2++)
                        MMA_F16(oa[mt][g * 2 + s2], pf[mt], vf[g][2 * s2], vf[g][2 * s2 + 1]);
        }
    }

    // finalize
    #pragma unroll
    for (int mt = 0; mt < 2; mt++) {
        lr[mt][0] += __shfl_xor_sync(0xFFFFFFFFu, lr[mt][0], 1);
        lr[mt][0] += __shfl_xor_sync(0xFFFFFFFFu, lr[mt][0], 2);
        lr[mt][1] += __shfl_xor_sync(0xFFFFFFFFu, lr[mt][1], 1);
        lr[mt][1] += __shfl_xor_sync(0xFFFFFFFFu, lr[mt][1], 2);
        const float inv0 = 1.f / lr[mt][0], inv1 = 1.f / lr[mt][1];

        const int r0 = m0 + wid * 32 + mt * 16 + (lane >> 2);
        const int cb = h * 64 + (lane & 3) * 2;
        #pragma unroll
        for (int n8 = 0; n8 < 8; n8++) {
            const int col = cb + n8 * 8;
            const size_t i0 = (size_t)(b * SEQ + r0) * CDIM + col;
            const size_t i1 = i0 + (size_t)8 * CDIM;
            *(uint32_t*)(g_a + i0) = pack2h(oa[mt][n8][0] * inv0, oa[mt][n8][1] * inv0);
            *(uint32_t*)(g_a + i1) = pack2h(oa[mt][n8][2] * inv1, oa[mt][n8][3] * inv1);
        }
    }
}

// ---------------------------------------------------------------------------
// Launch
// ---------------------------------------------------------------------------
extern "C" void kernel_launch(void* const* d_in, const int* in_sizes, int n_in,
                              void* d_out, int out_size)
{
    (void)in_sizes; (void)n_in; (void)out_size;
    const float* x      = (const float*)d_in[0];
    const float* W_qkv  = (const float*)d_in[1];
    const float* b_qkv  = (const float*)d_in[2];
    const float* zeta   = (const float*)d_in[3];
    const float* W_proj = (const float*)d_in[4];
    const float* b_proj = (const float*)d_in[5];
    const unsigned char* mask = (const unsigned char*)d_in[6];
    float* out = (float*)d_out;

    cudaFuncSetAttribute(gemm_hmma_kernel<true>,
                         cudaFuncAttributeMaxDynamicSharedMemorySize, GEMM_SMEM);
    cudaFuncSetAttribute(gemm_hmma_kernel<false>,
                         cudaFuncAttributeMaxDynamicSharedMemorySize, GEMM_SMEM);
    cudaFuncSetAttribute(attn_hmma_kernel,
                         cudaFuncAttributeMaxDynamicSharedMemorySize, AT_SMEM);

    cvt_x_kernel<<<(MROWS * CDIM / 4 + 255) / 256, 256>>>(x);
    {
        dim3 tb(32, 8);
        wtrans_kernel<true ><<<dim3(QKVC / 32, CDIM / 32), tb>>>(W_qkv);
        wtrans_kernel<false><<<dim3(CDIM / 32, CDIM / 32), tb>>>(W_proj);
    }
    gemm_hmma_kernel<true><<<dim3(QKVC / 128, MROWS / 128), 128, GEMM_SMEM>>>(b_qkv, zeta, nullptr);
    attn_hmma_kernel<<<dim3(SEQ / 128, HEADS, BATCH), 128, AT_SMEM>>>(mask);
    gemm_hmma_kernel<false><<<dim3(CDIM / 128, MROWS / 128), 128, GEMM_SMEM>>>(b_proj, nullptr, out);
}